// round 8
// baseline (speedup 1.0000x reference)
#include <cuda_runtime.h>
#include <cuda_fp16.h>
#include <cstdint>
#include <math.h>

// ---------------------------------------------------------------------------
// MinGPT forward.  B=4, S=1024, D=1024, H=16, HS=64, L=4, DFF=4096, V=32000.
// Round 8: fp16 2-product GEMM with 128x256 CTA tile, 64x64 warp tiles,
//          x4-trans B ldmatrix (2x MMA/ldsm ratio).
// ---------------------------------------------------------------------------

#define B_  4
#define S_  1024
#define D_  1024
#define H_  16
#define HS_ 64
#define L_  4
#define DFF_ 4096
#define V_  32000
#define M_  (B_ * S_)
#define MD_ ((size_t)M_ * D_)
#define EPS_ 1e-5f
#define SCALE_ 0.03125f        // D^-0.5 = 1/32 (reference uses d_model)

// ------------------------- scratch -----------------------------------------
__device__ float g_x  [M_ * D_];
__device__ float g_xn [M_ * D_];
__device__ float g_qkv[3 * M_ * D_];

__device__ __align__(16) __half g_ah[M_ * D_];
__device__ __align__(16) __half g_al[M_ * D_];
__device__ __align__(16) __half g_hh[M_ * DFF_];
__device__ __align__(16) __half g_hl[M_ * DFF_];

#define DD_      ((size_t)D_ * D_)
#define WQ_OFF_  ((size_t)0)
#define WK_OFF_  (4 * DD_)
#define WV_OFF_  (8 * DD_)
#define WO_OFF_  (12 * DD_)
#define W1_OFF_  (16 * DD_)
#define W2_OFF_  (32 * DD_)
#define WH_OFF_  (48 * DD_)
#define WT_TOT_  (48 * DD_ + (size_t)D_ * V_)
__device__ __align__(16) __half g_wh[WT_TOT_];

// ------------------------- PTX helpers --------------------------------------
__device__ __forceinline__ uint32_t smem_u32(const void* p) {
    uint32_t a;
    asm("{ .reg .u64 t; cvta.to.shared.u64 t, %1; cvt.u32.u64 %0, t; }"
        : "=r"(a) : "l"(p));
    return a;
}
#define CP16(dst, src) \
    asm volatile("cp.async.cg.shared.global [%0], [%1], 16;" :: "r"(dst), "l"(src))
#define CPCOMMIT() asm volatile("cp.async.commit_group;" ::: "memory")
#define CPWAIT0()  asm volatile("cp.async.wait_group 0;" ::: "memory")
#define CPWAIT1()  asm volatile("cp.async.wait_group 1;" ::: "memory")

__device__ __forceinline__ void ldsm4(uint32_t* r, uint32_t addr) {
    asm volatile("ldmatrix.sync.aligned.m8n8.x4.shared.b16 {%0,%1,%2,%3}, [%4];"
        : "=r"(r[0]), "=r"(r[1]), "=r"(r[2]), "=r"(r[3]) : "r"(addr));
}
__device__ __forceinline__ void ldsm4t(uint32_t* r, uint32_t addr) {
    asm volatile("ldmatrix.sync.aligned.m8n8.x4.trans.shared.b16 {%0,%1,%2,%3}, [%4];"
        : "=r"(r[0]), "=r"(r[1]), "=r"(r[2]), "=r"(r[3]) : "r"(addr));
}
__device__ __forceinline__ void mma16816(float* d, const uint32_t* a, const uint32_t* b) {
    asm volatile(
        "mma.sync.aligned.m16n8k16.row.col.f32.f16.f16.f32 "
        "{%0,%1,%2,%3}, {%4,%5,%6,%7}, {%8,%9}, {%0,%1,%2,%3};"
        : "+f"(d[0]), "+f"(d[1]), "+f"(d[2]), "+f"(d[3])
        : "r"(a[0]), "r"(a[1]), "r"(a[2]), "r"(a[3]), "r"(b[0]), "r"(b[1]));
}

// ------------------------- embedding ----------------------------------------
__global__ __launch_bounds__(256) void embed_k(
    const int* __restrict__ idx, const float4* __restrict__ tok,
    const float4* __restrict__ pos, float4* __restrict__ x)
{
    int row = blockIdx.x;
    int s   = row & (S_ - 1);
    int t   = idx[row];
    int c   = threadIdx.x;
    float4 tv = tok[(size_t)t * (D_ / 4) + c];
    float4 pv = pos[(size_t)s * (D_ / 4) + c];
    float4 o;
    o.x = tv.x + pv.x; o.y = tv.y + pv.y; o.z = tv.z + pv.z; o.w = tv.w + pv.w;
    x[(size_t)row * (D_ / 4) + c] = o;
}

// ------------------------- layer norm + fused fp16 split ---------------------
__global__ __launch_bounds__(256) void layernorm_k(
    const float4* __restrict__ x, const float4* __restrict__ g,
    const float4* __restrict__ bb, float4* __restrict__ y,
    __half2* __restrict__ oh, __half2* __restrict__ ol)
{
    int row = blockIdx.x;
    int tid = threadIdx.x;
    __shared__ float red[256];

    float4 xv = x[(size_t)row * 256 + tid];
    float s = xv.x + xv.y + xv.z + xv.w;
    red[tid] = s; __syncthreads();
    #pragma unroll
    for (int st = 128; st > 0; st >>= 1) {
        if (tid < st) red[tid] += red[tid + st];
        __syncthreads();
    }
    float mu = red[0] * (1.0f / D_);
    __syncthreads();

    float dx = xv.x - mu, dy = xv.y - mu, dz = xv.z - mu, dw = xv.w - mu;
    float s2 = dx * dx + dy * dy + dz * dz + dw * dw;
    red[tid] = s2; __syncthreads();
    #pragma unroll
    for (int st = 128; st > 0; st >>= 1) {
        if (tid < st) red[tid] += red[tid + st];
        __syncthreads();
    }
    float inv = rsqrtf(red[0] * (1.0f / D_) + EPS_);

    float4 gv = g[tid], bv = bb[tid];
    float4 o;
    o.x = dx * inv * gv.x + bv.x;
    o.y = dy * inv * gv.y + bv.y;
    o.z = dz * inv * gv.z + bv.z;
    o.w = dw * inv * gv.w + bv.w;
    size_t i = (size_t)row * 256 + tid;
    y[i] = o;

    __half hx = __float2half_rn(o.x), hy = __float2half_rn(o.y);
    __half hz = __float2half_rn(o.z), hw = __float2half_rn(o.w);
    oh[2 * i]     = __halves2half2(hx, hy);
    oh[2 * i + 1] = __halves2half2(hz, hw);
    ol[2 * i]     = __halves2half2(__float2half_rn(o.x - __half2float(hx)),
                                   __float2half_rn(o.y - __half2float(hy)));
    ol[2 * i + 1] = __halves2half2(__float2half_rn(o.z - __half2float(hz)),
                                   __float2half_rn(o.w - __half2float(hw)));
}

// ------------------------- fp32 -> single fp16 (weights) ---------------------
__global__ __launch_bounds__(256) void wsplit_k(
    const float4* __restrict__ x, __half2* __restrict__ h, int n4)
{
    int i = blockIdx.x * 256 + threadIdx.x;
    if (i >= n4) return;
    float4 v = x[i];
    h[2 * i]     = __halves2half2(__float2half_rn(v.x), __float2half_rn(v.y));
    h[2 * i + 1] = __halves2half2(__float2half_rn(v.z), __float2half_rn(v.w));
}

// ------------------------- mma.sync GEMM ------------------------------------
// C[M,N] = (Ah+Al)[M,K] @ B[K,N]  (+bias)(+res)(relu)(splitout),  fp16 in.
// CTA 128x256, BK=64.  8 warps = 2(M) x 4(N), warp tile 64x64.
// A: 128B rows + SW128; B: 512B rows, chunk^k swizzle; B frags via x4 trans.
#define ATILEB_ 16384
#define BTILEB_ 32768
#define BUFB_   (2 * ATILEB_ + BTILEB_)    // 64 KB
#define SMTOT_  (2 * BUFB_)                // 128 KB

template<bool BIAS, bool RES, bool RELU, bool OSPLIT>
__global__ __launch_bounds__(256, 1) void mma_gemm_k(
    int M, int N, int K,
    const __half* __restrict__ Ah, const __half* __restrict__ Al,
    const __half* __restrict__ Bw,
    const float* __restrict__ bias, const float* __restrict__ res,
    float* __restrict__ C,
    __half2* __restrict__ Oh, __half2* __restrict__ Ol,
    size_t bzS, size_t czS)
{
    extern __shared__ char smem[];
    const uint32_t sb = smem_u32(smem);
    const int tid = threadIdx.x, wid = tid >> 5, lane = tid & 31;
    const int mb = blockIdx.x, nb = blockIdx.y;
    Bw += blockIdx.z * bzS;
    C  += blockIdx.z * czS;
    const size_t ar0 = (size_t)mb * 128, bc0 = (size_t)nb * 256;
    const int wm = (wid >> 2) * 64, wn = (wid & 3) * 64;

    float acc[4][8][4];
    #pragma unroll
    for (int i = 0; i < 4; i++)
        #pragma unroll
        for (int j = 0; j < 8; j++)
            #pragma unroll
            for (int e = 0; e < 4; e++) acc[i][j][e] = 0.0f;

    const int nch = K >> 6;

    auto fill = [&](int buf, int c) {
        const size_t kof = (size_t)c << 6;
        const uint32_t bb = sb + buf * BUFB_;
        // A tiles: 128 rows x 64 fp16 (128B rows, SW128)
        #pragma unroll
        for (int i = 0; i < 4; i++) {
            int id = tid + 256 * i;          // 0..1023
            int r  = id >> 3;
            int cx = id & 7;
            uint32_t so = (uint32_t)(r * 128 + cx * 16);
            so ^= (so >> 3) & 0x70;
            size_t ai = (ar0 + r) * (size_t)K + kof + cx * 8;
            CP16(bb + 0 * ATILEB_ + so, Ah + ai);
            CP16(bb + 1 * ATILEB_ + so, Al + ai);
        }
        // B tile: 64 k-rows x 256 n (512B rows, chunk^kr swizzle)
        #pragma unroll
        for (int i = 0; i < 8; i++) {
            int id = tid + 256 * i;          // 0..2047
            int kr = id >> 5;                // 0..63
            int cx = id & 31;                // 16B chunk (8 n cols)
            uint32_t so = (uint32_t)(kr * 512 + ((cx ^ (kr & 31)) * 16));
            size_t bi = (kof + kr) * (size_t)N + bc0 + cx * 8;
            CP16(bb + 2 * ATILEB_ + so, Bw + bi);
        }
    };

    fill(0, 0); CPCOMMIT();

    uint32_t fa_h[4][4], fa_l[4][4], fb[8][2];
    const int arow = wm + (lane & 15);
    const int akb  = (lane >> 4) * 16;
    const int krl  = lane & 15;
    const int nsel = lane >> 4;              // 0/1: which n-8-group in the x4

    for (int c = 0; c < nch; c++) {
        if (c + 1 < nch) { fill((c + 1) & 1, c + 1); CPCOMMIT(); CPWAIT1(); }
        else             { CPWAIT0(); }
        __syncthreads();

        const uint32_t base = sb + (c & 1) * BUFB_;
        #pragma unroll
        for (int ks = 0; ks < 4; ks++) {
            #pragma unroll
            for (int i = 0; i < 4; i++) {
                uint32_t so = (uint32_t)((arow + i * 16) * 128 + ks * 32 + akb);
                so ^= (so >> 3) & 0x70;
                ldsm4(fa_h[i], base + 0 * ATILEB_ + so);
                ldsm4(fa_l[i], base + 1 * ATILEB_ + so);
            }
            const uint32_t krow = (uint32_t)(ks * 16 + krl);
            #pragma unroll
            for (int j2 = 0; j2 < 4; j2++) {
                // x4 trans: lanes 0-15 -> n-8-group (wn/8 + 2*j2),
                //           lanes 16-31 -> group +1.  regs r0,r1 = fb[2*j2],
                //           r2,r3 = fb[2*j2+1].
                uint32_t cx = (uint32_t)((wn >> 3) + 2 * j2 + nsel);
                uint32_t so = krow * 512 + ((cx ^ (krow & 31)) * 16);
                uint32_t r[4];
                ldsm4t(r, base + 2 * ATILEB_ + so);
                fb[2 * j2 + 0][0] = r[0]; fb[2 * j2 + 0][1] = r[1];
                fb[2 * j2 + 1][0] = r[2]; fb[2 * j2 + 1][1] = r[3];
            }
            #pragma unroll
            for (int i = 0; i < 4; i++)
                #pragma unroll
                for (int j = 0; j < 8; j++)
                    mma16816(acc[i][j], fa_h[i], fb[j]);
            #pragma unroll
            for (int i = 0; i < 4; i++)
                #pragma unroll
                for (int j = 0; j < 8; j++)
                    mma16816(acc[i][j], fa_l[i], fb[j]);
        }
        __syncthreads();
    }

    // ---- epilogue ----
    const int g  = lane >> 2, tg = lane & 3;
    const size_t row0 = ar0 + wm, col0 = bc0 + wn;
    #pragma unroll
    for (int i = 0; i < 4; i++) {
        #pragma unroll
        for (int j = 0; j < 8; j++) {
            size_t col = col0 + j * 8 + tg * 2;
            float bx = 0.0f, by = 0.0f;
            if (BIAS) { bx = bias[col]; by = bias[col + 1]; }
            #pragma unroll
            for (int half = 0; half < 2; half++) {
                size_t row = row0 + i * 16 + g + half * 8;
                float vx = acc[i][j][2 * half + 0] + bx;
                float vy = acc[i][j][2 * half + 1] + by;
                size_t gi = row * (size_t)N + col;
                if (RES) { vx += res[gi]; vy += res[gi + 1]; }
                if (RELU) { vx = fmaxf(vx, 0.0f); vy = fmaxf(vy, 0.0f); }
                if (OSPLIT) {
                    __half hx = __float2half_rn(vx);
                    __half hy = __float2half_rn(vy);
                    Oh[gi >> 1] = __halves2half2(hx, hy);
                    Ol[gi >> 1] = __halves2half2(
                        __float2half_rn(vx - __half2float(hx)),
                        __float2half_rn(vy - __half2float(hy)));
                } else {
                    float2 o; o.x = vx; o.y = vy;
                    *(float2*)(C + gi) = o;
                }
            }
        }
    }
}

// ------------------------- query-tiled causal attention (QT=16) -------------
#define QT_   16
#define SPAD_ 1032
#define ATT_SMEM_ ((QT_ * SPAD_ + QT_) * 4)
__global__ __launch_bounds__(256) void attention2_k(
    const float* __restrict__ q, const float* __restrict__ k,
    const float* __restrict__ v,
    __half* __restrict__ oh, __half* __restrict__ ol)
{
    extern __shared__ float S[];
    float* Rinv = S + QT_ * SPAD_;

    int qt = blockIdx.x, h = blockIdx.y, b = blockIdx.z;
    int q0 = qt * QT_;
    int nmax = q0 + QT_;
    int tid = threadIdx.x;

    {
        int qi = tid & 15;
        int jg = tid >> 4;
        const float* qp = q + (((size_t)b * S_ + q0 + qi) * H_ + h) * HS_;
        float4 qr[16];
        #pragma unroll
        for (int d = 0; d < 16; d++) qr[d] = *(const float4*)(qp + 4 * d);
        int nq = q0 + qi + 1;
        for (int j = jg; j < nq; j += 16) {
            const float* kp = k + (((size_t)b * S_ + j) * H_ + h) * HS_;
            float dot = 0.0f;
            #pragma unroll
            for (int d = 0; d < 16; d++) {
                float4 kk = *(const float4*)(kp + 4 * d);
                dot += kk.x * qr[d].x + kk.y * qr[d].y + kk.z * qr[d].z + kk.w * qr[d].w;
            }
            S[qi * SPAD_ + j] = dot * SCALE_;
        }
    }
    __syncthreads();

    {
        int w = tid >> 5, l = tid & 31;
        #pragma unroll
        for (int qq = 0; qq < 2; qq++) {
            int qi = 2 * w + qq;
            int nq = q0 + qi + 1;
            float m = -1e30f;
            for (int j = l; j < nq; j += 32) m = fmaxf(m, S[qi * SPAD_ + j]);
            #pragma unroll
            for (int st = 16; st > 0; st >>= 1)
                m = fmaxf(m, __shfl_xor_sync(0xffffffff, m, st));
            float sum = 0.0f;
            for (int j = l; j < nq; j += 32) {
                float e = __expf(S[qi * SPAD_ + j] - m);
                S[qi * SPAD_ + j] = e;
                sum += e;
            }
            #pragma unroll
            for (int st = 16; st > 0; st >>= 1)
                sum += __shfl_xor_sync(0xffffffff, sum, st);
            for (int j = nq + l; j < nmax; j += 32) S[qi * SPAD_ + j] = 0.0f;
            if (l == 0) Rinv[qi] = 1.0f / sum;
        }
    }
    __syncthreads();

    float acc[QT_][4];
    {
        int d4 = tid & 15;
        int jg = tid >> 4;
        #pragma unroll
        for (int qi = 0; qi < QT_; qi++)
            #pragma unroll
            for (int cc = 0; cc < 4; cc++) acc[qi][cc] = 0.0f;
        for (int j = jg; j < nmax; j += 16) {
            float4 vv = *(const float4*)(v + (((size_t)b * S_ + j) * H_ + h) * HS_ + d4 * 4);
            #pragma unroll
            for (int qi = 0; qi < QT_; qi++) {
                float p = S[qi * SPAD_ + j];
                acc[qi][0] += p * vv.x; acc[qi][1] += p * vv.y;
                acc[qi][2] += p * vv.z; acc[qi][3] += p * vv.w;
            }
        }
    }
    __syncthreads();
    {
        int d4 = tid & 15;
        int jg = tid >> 4;
        #pragma unroll
        for (int qi = 0; qi < QT_; qi++)
            #pragma unroll
            for (int cc = 0; cc < 4; cc++)
                S[jg * 1024 + qi * 64 + d4 * 4 + cc] = acc[qi][cc];
    }
    __syncthreads();
    {
        #pragma unroll
        for (int e = tid; e < 1024; e += 256) {
            int qi = e >> 6, d = e & 63;
            float sum = 0.0f;
            #pragma unroll
            for (int jg = 0; jg < 16; jg++) sum += S[jg * 1024 + e];
            float val = sum * Rinv[qi];
            size_t gi = (((size_t)b * S_ + q0 + qi) * H_ + h) * HS_ + d;
            __half hv = __float2half_rn(val);
            oh[gi] = hv;
            ol[gi] = __float2half_rn(val - __half2float(hv));
        }
    }
}

// ------------------------- driver -------------------------------------------
extern "C" void kernel_launch(void* const* d_in, const int* in_sizes, int n_in,
                              void* d_out, int out_size)
{
    const int*   idx   = (const int*)  d_in[0];
    const float* tok   = (const float*)d_in[1];
    const float* pos   = (const float*)d_in[2];
    const float* ln1g  = (const float*)d_in[3];
    const float* ln1b  = (const float*)d_in[4];
    const float* ln2g  = (const float*)d_in[5];
    const float* ln2b  = (const float*)d_in[6];
    const float* wq    = (const float*)d_in[7];
    const float* wk    = (const float*)d_in[8];
    const float* wv    = (const float*)d_in[9];
    const float* wo    = (const float*)d_in[10];
    const float* bo    = (const float*)d_in[11];
    const float* w1    = (const float*)d_in[12];
    const float* b1    = (const float*)d_in[13];
    const float* w2    = (const float*)d_in[14];
    const float* b2    = (const float*)d_in[15];
    const float* lnfg  = (const float*)d_in[16];
    const float* lnfb  = (const float*)d_in[17];
    const float* whead = (const float*)d_in[18];
    const float* bhead = (const float*)d_in[19];
    float* out = (float*)d_out;

    float *x, *xn, *qkv;
    __half *ah, *al, *hh, *hl, *wh;
    cudaGetSymbolAddress((void**)&x,   g_x);
    cudaGetSymbolAddress((void**)&xn,  g_xn);
    cudaGetSymbolAddress((void**)&qkv, g_qkv);
    cudaGetSymbolAddress((void**)&ah,  g_ah);
    cudaGetSymbolAddress((void**)&al,  g_al);
    cudaGetSymbolAddress((void**)&hh,  g_hh);
    cudaGetSymbolAddress((void**)&hl,  g_hl);
    cudaGetSymbolAddress((void**)&wh,  g_wh);

    cudaFuncSetAttribute(mma_gemm_k<false,false,false,false>, cudaFuncAttributeMaxDynamicSharedMemorySize, SMTOT_);
    cudaFuncSetAttribute(mma_gemm_k<true,true,false,false>,   cudaFuncAttributeMaxDynamicSharedMemorySize, SMTOT_);
    cudaFuncSetAttribute(mma_gemm_k<true,false,true,true>,    cudaFuncAttributeMaxDynamicSharedMemorySize, SMTOT_);
    cudaFuncSetAttribute(mma_gemm_k<true,false,false,false>,  cudaFuncAttributeMaxDynamicSharedMemorySize, SMTOT_);
    cudaFuncSetAttribute(attention2_k, cudaFuncAttributeMaxDynamicSharedMemorySize, ATT_SMEM_);

    dim3 blk(256);

    // ---- weight fp16 conversion ----
    {
        int nQ = (int)(4 * DD_ / 4);
        int nF = (int)(16 * DD_ / 4);
        int nH = (int)((size_t)D_ * V_ / 4);
        wsplit_k<<<(nQ + 255)/256, blk>>>((const float4*)wq, (__half2*)(wh + WQ_OFF_), nQ);
        wsplit_k<<<(nQ + 255)/256, blk>>>((const float4*)wk, (__half2*)(wh + WK_OFF_), nQ);
        wsplit_k<<<(nQ + 255)/256, blk>>>((const float4*)wv, (__half2*)(wh + WV_OFF_), nQ);
        wsplit_k<<<(nQ + 255)/256, blk>>>((const float4*)wo, (__half2*)(wh + WO_OFF_), nQ);
        wsplit_k<<<(nF + 255)/256, blk>>>((const float4*)w1, (__half2*)(wh + W1_OFF_), nF);
        wsplit_k<<<(nF + 255)/256, blk>>>((const float4*)w2, (__half2*)(wh + W2_OFF_), nF);
        wsplit_k<<<(nH + 255)/256, blk>>>((const float4*)whead, (__half2*)(wh + WH_OFF_), nH);
    }

    embed_k<<<M_, blk>>>(idx, (const float4*)tok, (const float4*)pos, (float4*)x);

    for (int l = 0; l < L_; l++) {
        size_t oq = WQ_OFF_ + (size_t)l * DD_;
        size_t oo = WO_OFF_ + (size_t)l * DD_;
        size_t o1 = W1_OFF_ + (size_t)l * 4 * DD_;
        size_t o2 = W2_OFF_ + (size_t)l * 4 * DD_;

        layernorm_k<<<M_, blk>>>((const float4*)x, (const float4*)(ln1g + l * D_),
                                 (const float4*)(ln1b + l * D_), (float4*)xn,
                                 (__half2*)ah, (__half2*)al);

        // fused QKV
        mma_gemm_k<false,false,false,false><<<dim3(M_/128, D_/256, 3), blk, SMTOT_>>>(
            M_, D_, D_, ah, al, wh + oq, nullptr, nullptr, qkv,
            nullptr, nullptr, 4 * DD_, MD_);

        attention2_k<<<dim3(S_ / QT_, H_, B_), 256, ATT_SMEM_>>>(
            qkv, qkv + MD_, qkv + 2 * MD_, ah, al);

        // x = xn + att @ wo + bo
        mma_gemm_k<true,true,false,false><<<dim3(M_/128, D_/256), blk, SMTOT_>>>(
            M_, D_, D_, ah, al, wh + oo, bo + l * D_, xn, x,
            nullptr, nullptr, 0, 0);

        layernorm_k<<<M_, blk>>>((const float4*)x, (const float4*)(ln2g + l * D_),
                                 (const float4*)(ln2b + l * D_), (float4*)xn,
                                 (__half2*)ah, (__half2*)al);

        // h = relu(xn @ w1 + b1)  -> fp16 hi/lo directly
        mma_gemm_k<true,false,true,true><<<dim3(M_/128, DFF_/256), blk, SMTOT_>>>(
            M_, DFF_, D_, ah, al, wh + o1,
            b1 + (size_t)l * DFF_, nullptr, nullptr,
            (__half2*)hh, (__half2*)hl, 0, 0);

        // x = xn + h @ w2 + b2
        mma_gemm_k<true,true,false,false><<<dim3(M_/128, D_/256), blk, SMTOT_>>>(
            M_, D_, DFF_, hh, hl, wh + o2,
            b2 + l * D_, xn, x, nullptr, nullptr, 0, 0);
    }

    layernorm_k<<<M_, blk>>>((const float4*)x, (const float4*)lnfg,
                             (const float4*)lnfb, (float4*)xn,
                             (__half2*)ah, (__half2*)al);

    // logits = xn @ w_head + b_head
    mma_gemm_k<true,false,false,false><<<dim3(M_/128, V_/256), blk, SMTOT_>>>(
        M_, V_, D_, ah, al, wh + WH_OFF_,
        bhead, nullptr, out, nullptr, nullptr, 0, 0);
}

// round 9
// speedup vs baseline: 1.2333x; 1.2333x over previous
#include <cuda_runtime.h>
#include <cuda_fp16.h>
#include <cstdint>
#include <math.h>

// ---------------------------------------------------------------------------
// MinGPT forward.  B=4, S=1024, D=1024, H=16, HS=64, L=4, DFF=4096, V=32000.
// Round 9: single-product fp16 GEMM (A fp16, W fp16, fp32 accum).
// CTA 128x256, 64x64 warp tiles, x4-trans B, double-buffered cp.async.
// ---------------------------------------------------------------------------

#define B_  4
#define S_  1024
#define D_  1024
#define H_  16
#define HS_ 64
#define L_  4
#define DFF_ 4096
#define V_  32000
#define M_  (B_ * S_)
#define MD_ ((size_t)M_ * D_)
#define EPS_ 1e-5f
#define SCALE_ 0.03125f        // D^-0.5 = 1/32 (reference uses d_model)

// ------------------------- scratch -----------------------------------------
__device__ float g_x  [M_ * D_];
__device__ float g_xn [M_ * D_];
__device__ float g_qkv[3 * M_ * D_];

__device__ __align__(16) __half g_ah[M_ * D_];
__device__ __align__(16) __half g_hh[M_ * DFF_];

#define DD_      ((size_t)D_ * D_)
#define WQ_OFF_  ((size_t)0)
#define WK_OFF_  (4 * DD_)
#define WV_OFF_  (8 * DD_)
#define WO_OFF_  (12 * DD_)
#define W1_OFF_  (16 * DD_)
#define W2_OFF_  (32 * DD_)
#define WH_OFF_  (48 * DD_)
#define WT_TOT_  (48 * DD_ + (size_t)D_ * V_)
__device__ __align__(16) __half g_wh[WT_TOT_];

// ------------------------- PTX helpers --------------------------------------
__device__ __forceinline__ uint32_t smem_u32(const void* p) {
    uint32_t a;
    asm("{ .reg .u64 t; cvta.to.shared.u64 t, %1; cvt.u32.u64 %0, t; }"
        : "=r"(a) : "l"(p));
    return a;
}
#define CP16(dst, src) \
    asm volatile("cp.async.cg.shared.global [%0], [%1], 16;" :: "r"(dst), "l"(src))
#define CPCOMMIT() asm volatile("cp.async.commit_group;" ::: "memory")
#define CPWAIT0()  asm volatile("cp.async.wait_group 0;" ::: "memory")
#define CPWAIT1()  asm volatile("cp.async.wait_group 1;" ::: "memory")

__device__ __forceinline__ void ldsm4(uint32_t* r, uint32_t addr) {
    asm volatile("ldmatrix.sync.aligned.m8n8.x4.shared.b16 {%0,%1,%2,%3}, [%4];"
        : "=r"(r[0]), "=r"(r[1]), "=r"(r[2]), "=r"(r[3]) : "r"(addr));
}
__device__ __forceinline__ void ldsm4t(uint32_t* r, uint32_t addr) {
    asm volatile("ldmatrix.sync.aligned.m8n8.x4.trans.shared.b16 {%0,%1,%2,%3}, [%4];"
        : "=r"(r[0]), "=r"(r[1]), "=r"(r[2]), "=r"(r[3]) : "r"(addr));
}
__device__ __forceinline__ void mma16816(float* d, const uint32_t* a, const uint32_t* b) {
    asm volatile(
        "mma.sync.aligned.m16n8k16.row.col.f32.f16.f16.f32 "
        "{%0,%1,%2,%3}, {%4,%5,%6,%7}, {%8,%9}, {%0,%1,%2,%3};"
        : "+f"(d[0]), "+f"(d[1]), "+f"(d[2]), "+f"(d[3])
        : "r"(a[0]), "r"(a[1]), "r"(a[2]), "r"(a[3]), "r"(b[0]), "r"(b[1]));
}

// ------------------------- embedding ----------------------------------------
__global__ __launch_bounds__(256) void embed_k(
    const int* __restrict__ idx, const float4* __restrict__ tok,
    const float4* __restrict__ pos, float4* __restrict__ x)
{
    int row = blockIdx.x;
    int s   = row & (S_ - 1);
    int t   = idx[row];
    int c   = threadIdx.x;
    float4 tv = tok[(size_t)t * (D_ / 4) + c];
    float4 pv = pos[(size_t)s * (D_ / 4) + c];
    float4 o;
    o.x = tv.x + pv.x; o.y = tv.y + pv.y; o.z = tv.z + pv.z; o.w = tv.w + pv.w;
    x[(size_t)row * (D_ / 4) + c] = o;
}

// ------------------------- layer norm + fused fp16 convert -------------------
__global__ __launch_bounds__(256) void layernorm_k(
    const float4* __restrict__ x, const float4* __restrict__ g,
    const float4* __restrict__ bb, float4* __restrict__ y,
    __half2* __restrict__ oh)
{
    int row = blockIdx.x;
    int tid = threadIdx.x;
    __shared__ float red[256];

    float4 xv = x[(size_t)row * 256 + tid];
    float s = xv.x + xv.y + xv.z + xv.w;
    red[tid] = s; __syncthreads();
    #pragma unroll
    for (int st = 128; st > 0; st >>= 1) {
        if (tid < st) red[tid] += red[tid + st];
        __syncthreads();
    }
    float mu = red[0] * (1.0f / D_);
    __syncthreads();

    float dx = xv.x - mu, dy = xv.y - mu, dz = xv.z - mu, dw = xv.w - mu;
    float s2 = dx * dx + dy * dy + dz * dz + dw * dw;
    red[tid] = s2; __syncthreads();
    #pragma unroll
    for (int st = 128; st > 0; st >>= 1) {
        if (tid < st) red[tid] += red[tid + st];
        __syncthreads();
    }
    float inv = rsqrtf(red[0] * (1.0f / D_) + EPS_);

    float4 gv = g[tid], bv = bb[tid];
    float4 o;
    o.x = dx * inv * gv.x + bv.x;
    o.y = dy * inv * gv.y + bv.y;
    o.z = dz * inv * gv.z + bv.z;
    o.w = dw * inv * gv.w + bv.w;
    size_t i = (size_t)row * 256 + tid;
    y[i] = o;

    oh[2 * i]     = __halves2half2(__float2half_rn(o.x), __float2half_rn(o.y));
    oh[2 * i + 1] = __halves2half2(__float2half_rn(o.z), __float2half_rn(o.w));
}

// ------------------------- fp32 -> fp16 (weights) ----------------------------
__global__ __launch_bounds__(256) void wsplit_k(
    const float4* __restrict__ x, __half2* __restrict__ h, int n4)
{
    int i = blockIdx.x * 256 + threadIdx.x;
    if (i >= n4) return;
    float4 v = x[i];
    h[2 * i]     = __halves2half2(__float2half_rn(v.x), __float2half_rn(v.y));
    h[2 * i + 1] = __halves2half2(__float2half_rn(v.z), __float2half_rn(v.w));
}

// ------------------------- mma.sync GEMM ------------------------------------
// C[M,N] = A[M,K] @ B[K,N]  (+bias)(+res)(relu)(fp16out),  fp16 in, fp32 acc.
// CTA 128x256, BK=64.  8 warps = 2(M) x 4(N), warp tile 64x64.
#define ATILEB_ 16384
#define BTILEB_ 32768
#define BUFB_   (ATILEB_ + BTILEB_)        // 48 KB
#define SMTOT_  (2 * BUFB_)                // 96 KB

template<bool BIAS, bool RES, bool RELU, bool OHALF>
__global__ __launch_bounds__(256, 1) void mma_gemm_k(
    int M, int N, int K,
    const __half* __restrict__ Ah,
    const __half* __restrict__ Bw,
    const float* __restrict__ bias, const float* __restrict__ res,
    float* __restrict__ C,
    __half2* __restrict__ Oh,
    size_t bzS, size_t czS)
{
    extern __shared__ char smem[];
    const uint32_t sb = smem_u32(smem);
    const int tid = threadIdx.x, wid = tid >> 5, lane = tid & 31;
    const int mb = blockIdx.x, nb = blockIdx.y;
    Bw += blockIdx.z * bzS;
    C  += blockIdx.z * czS;
    const size_t ar0 = (size_t)mb * 128, bc0 = (size_t)nb * 256;
    const int wm = (wid >> 2) * 64, wn = (wid & 3) * 64;

    float acc[4][8][4];
    #pragma unroll
    for (int i = 0; i < 4; i++)
        #pragma unroll
        for (int j = 0; j < 8; j++)
            #pragma unroll
            for (int e = 0; e < 4; e++) acc[i][j][e] = 0.0f;

    const int nch = K >> 6;

    auto fill = [&](int buf, int c) {
        const size_t kof = (size_t)c << 6;
        const uint32_t bb = sb + buf * BUFB_;
        // A tile: 128 rows x 64 fp16 (128B rows, SW128)
        #pragma unroll
        for (int i = 0; i < 4; i++) {
            int id = tid + 256 * i;          // 0..1023
            int r  = id >> 3;
            int cx = id & 7;
            uint32_t so = (uint32_t)(r * 128 + cx * 16);
            so ^= (so >> 3) & 0x70;
            size_t ai = (ar0 + r) * (size_t)K + kof + cx * 8;
            CP16(bb + so, Ah + ai);
        }
        // B tile: 64 k-rows x 256 n (512B rows, chunk^kr swizzle)
        #pragma unroll
        for (int i = 0; i < 8; i++) {
            int id = tid + 256 * i;          // 0..2047
            int kr = id >> 5;                // 0..63
            int cx = id & 31;                // 16B chunk (8 n cols)
            uint32_t so = (uint32_t)(kr * 512 + ((cx ^ (kr & 31)) * 16));
            size_t bi = (kof + kr) * (size_t)N + bc0 + cx * 8;
            CP16(bb + ATILEB_ + so, Bw + bi);
        }
    };

    fill(0, 0); CPCOMMIT();

    uint32_t fa[4][4], fb[8][2];
    const int arow = wm + (lane & 15);
    const int akb  = (lane >> 4) * 16;
    const int krl  = lane & 15;
    const int nsel = lane >> 4;

    for (int c = 0; c < nch; c++) {
        if (c + 1 < nch) { fill((c + 1) & 1, c + 1); CPCOMMIT(); CPWAIT1(); }
        else             { CPWAIT0(); }
        __syncthreads();

        const uint32_t base = sb + (c & 1) * BUFB_;
        #pragma unroll
        for (int ks = 0; ks < 4; ks++) {
            #pragma unroll
            for (int i = 0; i < 4; i++) {
                uint32_t so = (uint32_t)((arow + i * 16) * 128 + ks * 32 + akb);
                so ^= (so >> 3) & 0x70;
                ldsm4(fa[i], base + so);
            }
            const uint32_t krow = (uint32_t)(ks * 16 + krl);
            #pragma unroll
            for (int j2 = 0; j2 < 4; j2++) {
                uint32_t cx = (uint32_t)((wn >> 3) + 2 * j2 + nsel);
                uint32_t so = krow * 512 + ((cx ^ (krow & 31)) * 16);
                uint32_t r[4];
                ldsm4t(r, base + ATILEB_ + so);
                fb[2 * j2 + 0][0] = r[0]; fb[2 * j2 + 0][1] = r[1];
                fb[2 * j2 + 1][0] = r[2]; fb[2 * j2 + 1][1] = r[3];
            }
            #pragma unroll
            for (int i = 0; i < 4; i++)
                #pragma unroll
                for (int j = 0; j < 8; j++)
                    mma16816(acc[i][j], fa[i], fb[j]);
        }
        __syncthreads();
    }

    // ---- epilogue ----
    const int g  = lane >> 2, tg = lane & 3;
    const size_t row0 = ar0 + wm, col0 = bc0 + wn;
    #pragma unroll
    for (int i = 0; i < 4; i++) {
        #pragma unroll
        for (int j = 0; j < 8; j++) {
            size_t col = col0 + j * 8 + tg * 2;
            float bx = 0.0f, by = 0.0f;
            if (BIAS) { bx = bias[col]; by = bias[col + 1]; }
            #pragma unroll
            for (int half = 0; half < 2; half++) {
                size_t row = row0 + i * 16 + g + half * 8;
                float vx = acc[i][j][2 * half + 0] + bx;
                float vy = acc[i][j][2 * half + 1] + by;
                size_t gi = row * (size_t)N + col;
                if (RES) { vx += res[gi]; vy += res[gi + 1]; }
                if (RELU) { vx = fmaxf(vx, 0.0f); vy = fmaxf(vy, 0.0f); }
                if (OHALF) {
                    Oh[gi >> 1] = __halves2half2(__float2half_rn(vx),
                                                 __float2half_rn(vy));
                } else {
                    float2 o; o.x = vx; o.y = vy;
                    *(float2*)(C + gi) = o;
                }
            }
        }
    }
}

// ------------------------- query-tiled causal attention (QT=16) -------------
#define QT_   16
#define SPAD_ 1032
#define ATT_SMEM_ ((QT_ * SPAD_ + QT_) * 4)
__global__ __launch_bounds__(256) void attention2_k(
    const float* __restrict__ q, const float* __restrict__ k,
    const float* __restrict__ v,
    __half* __restrict__ oh)
{
    extern __shared__ float S[];
    float* Rinv = S + QT_ * SPAD_;

    int qt = blockIdx.x, h = blockIdx.y, b = blockIdx.z;
    int q0 = qt * QT_;
    int nmax = q0 + QT_;
    int tid = threadIdx.x;

    {
        int qi = tid & 15;
        int jg = tid >> 4;
        const float* qp = q + (((size_t)b * S_ + q0 + qi) * H_ + h) * HS_;
        float4 qr[16];
        #pragma unroll
        for (int d = 0; d < 16; d++) qr[d] = *(const float4*)(qp + 4 * d);
        int nq = q0 + qi + 1;
        for (int j = jg; j < nq; j += 16) {
            const float* kp = k + (((size_t)b * S_ + j) * H_ + h) * HS_;
            float dot = 0.0f;
            #pragma unroll
            for (int d = 0; d < 16; d++) {
                float4 kk = *(const float4*)(kp + 4 * d);
                dot += kk.x * qr[d].x + kk.y * qr[d].y + kk.z * qr[d].z + kk.w * qr[d].w;
            }
            S[qi * SPAD_ + j] = dot * SCALE_;
        }
    }
    __syncthreads();

    {
        int w = tid >> 5, l = tid & 31;
        #pragma unroll
        for (int qq = 0; qq < 2; qq++) {
            int qi = 2 * w + qq;
            int nq = q0 + qi + 1;
            float m = -1e30f;
            for (int j = l; j < nq; j += 32) m = fmaxf(m, S[qi * SPAD_ + j]);
            #pragma unroll
            for (int st = 16; st > 0; st >>= 1)
                m = fmaxf(m, __shfl_xor_sync(0xffffffff, m, st));
            float sum = 0.0f;
            for (int j = l; j < nq; j += 32) {
                float e = __expf(S[qi * SPAD_ + j] - m);
                S[qi * SPAD_ + j] = e;
                sum += e;
            }
            #pragma unroll
            for (int st = 16; st > 0; st >>= 1)
                sum += __shfl_xor_sync(0xffffffff, sum, st);
            for (int j = nq + l; j < nmax; j += 32) S[qi * SPAD_ + j] = 0.0f;
            if (l == 0) Rinv[qi] = 1.0f / sum;
        }
    }
    __syncthreads();

    float acc[QT_][4];
    {
        int d4 = tid & 15;
        int jg = tid >> 4;
        #pragma unroll
        for (int qi = 0; qi < QT_; qi++)
            #pragma unroll
            for (int cc = 0; cc < 4; cc++) acc[qi][cc] = 0.0f;
        for (int j = jg; j < nmax; j += 16) {
            float4 vv = *(const float4*)(v + (((size_t)b * S_ + j) * H_ + h) * HS_ + d4 * 4);
            #pragma unroll
            for (int qi = 0; qi < QT_; qi++) {
                float p = S[qi * SPAD_ + j];
                acc[qi][0] += p * vv.x; acc[qi][1] += p * vv.y;
                acc[qi][2] += p * vv.z; acc[qi][3] += p * vv.w;
            }
        }
    }
    __syncthreads();
    {
        int d4 = tid & 15;
        int jg = tid >> 4;
        #pragma unroll
        for (int qi = 0; qi < QT_; qi++)
            #pragma unroll
            for (int cc = 0; cc < 4; cc++)
                S[jg * 1024 + qi * 64 + d4 * 4 + cc] = acc[qi][cc];
    }
    __syncthreads();
    {
        #pragma unroll
        for (int e = tid; e < 1024; e += 256) {
            int qi = e >> 6, d = e & 63;
            float sum = 0.0f;
            #pragma unroll
            for (int jg = 0; jg < 16; jg++) sum += S[jg * 1024 + e];
            float val = sum * Rinv[qi];
            size_t gi = (((size_t)b * S_ + q0 + qi) * H_ + h) * HS_ + d;
            oh[gi] = __float2half_rn(val);
        }
    }
}

// ------------------------- driver -------------------------------------------
extern "C" void kernel_launch(void* const* d_in, const int* in_sizes, int n_in,
                              void* d_out, int out_size)
{
    const int*   idx   = (const int*)  d_in[0];
    const float* tok   = (const float*)d_in[1];
    const float* pos   = (const float*)d_in[2];
    const float* ln1g  = (const float*)d_in[3];
    const float* ln1b  = (const float*)d_in[4];
    const float* ln2g  = (const float*)d_in[5];
    const float* ln2b  = (const float*)d_in[6];
    const float* wq    = (const float*)d_in[7];
    const float* wk    = (const float*)d_in[8];
    const float* wv    = (const float*)d_in[9];
    const float* wo    = (const float*)d_in[10];
    const float* bo    = (const float*)d_in[11];
    const float* w1    = (const float*)d_in[12];
    const float* b1    = (const float*)d_in[13];
    const float* w2    = (const float*)d_in[14];
    const float* b2    = (const float*)d_in[15];
    const float* lnfg  = (const float*)d_in[16];
    const float* lnfb  = (const float*)d_in[17];
    const float* whead = (const float*)d_in[18];
    const float* bhead = (const float*)d_in[19];
    float* out = (float*)d_out;

    float *x, *xn, *qkv;
    __half *ah, *hh, *wh;
    cudaGetSymbolAddress((void**)&x,   g_x);
    cudaGetSymbolAddress((void**)&xn,  g_xn);
    cudaGetSymbolAddress((void**)&qkv, g_qkv);
    cudaGetSymbolAddress((void**)&ah,  g_ah);
    cudaGetSymbolAddress((void**)&hh,  g_hh);
    cudaGetSymbolAddress((void**)&wh,  g_wh);

    cudaFuncSetAttribute(mma_gemm_k<false,false,false,false>, cudaFuncAttributeMaxDynamicSharedMemorySize, SMTOT_);
    cudaFuncSetAttribute(mma_gemm_k<true,true,false,false>,   cudaFuncAttributeMaxDynamicSharedMemorySize, SMTOT_);
    cudaFuncSetAttribute(mma_gemm_k<true,false,true,true>,    cudaFuncAttributeMaxDynamicSharedMemorySize, SMTOT_);
    cudaFuncSetAttribute(mma_gemm_k<true,false,false,false>,  cudaFuncAttributeMaxDynamicSharedMemorySize, SMTOT_);
    cudaFuncSetAttribute(attention2_k, cudaFuncAttributeMaxDynamicSharedMemorySize, ATT_SMEM_);

    dim3 blk(256);

    // ---- weight fp16 conversion ----
    {
        int nQ = (int)(4 * DD_ / 4);
        int nF = (int)(16 * DD_ / 4);
        int nH = (int)((size_t)D_ * V_ / 4);
        wsplit_k<<<(nQ + 255)/256, blk>>>((const float4*)wq, (__half2*)(wh + WQ_OFF_), nQ);
        wsplit_k<<<(nQ + 255)/256, blk>>>((const float4*)wk, (__half2*)(wh + WK_OFF_), nQ);
        wsplit_k<<<(nQ + 255)/256, blk>>>((const float4*)wv, (__half2*)(wh + WV_OFF_), nQ);
        wsplit_k<<<(nQ + 255)/256, blk>>>((const float4*)wo, (__half2*)(wh + WO_OFF_), nQ);
        wsplit_k<<<(nF + 255)/256, blk>>>((const float4*)w1, (__half2*)(wh + W1_OFF_), nF);
        wsplit_k<<<(nF + 255)/256, blk>>>((const float4*)w2, (__half2*)(wh + W2_OFF_), nF);
        wsplit_k<<<(nH + 255)/256, blk>>>((const float4*)whead, (__half2*)(wh + WH_OFF_), nH);
    }

    embed_k<<<M_, blk>>>(idx, (const float4*)tok, (const float4*)pos, (float4*)x);

    for (int l = 0; l < L_; l++) {
        size_t oq = WQ_OFF_ + (size_t)l * DD_;
        size_t oo = WO_OFF_ + (size_t)l * DD_;
        size_t o1 = W1_OFF_ + (size_t)l * 4 * DD_;
        size_t o2 = W2_OFF_ + (size_t)l * 4 * DD_;

        layernorm_k<<<M_, blk>>>((const float4*)x, (const float4*)(ln1g + l * D_),
                                 (const float4*)(ln1b + l * D_), (float4*)xn,
                                 (__half2*)ah);

        // fused QKV
        mma_gemm_k<false,false,false,false><<<dim3(M_/128, D_/256, 3), blk, SMTOT_>>>(
            M_, D_, D_, ah, wh + oq, nullptr, nullptr, qkv,
            nullptr, 4 * DD_, MD_);

        attention2_k<<<dim3(S_ / QT_, H_, B_), 256, ATT_SMEM_>>>(
            qkv, qkv + MD_, qkv + 2 * MD_, ah);

        // x = xn + att @ wo + bo
        mma_gemm_k<true,true,false,false><<<dim3(M_/128, D_/256), blk, SMTOT_>>>(
            M_, D_, D_, ah, wh + oo, bo + l * D_, xn, x,
            nullptr, 0, 0);

        layernorm_k<<<M_, blk>>>((const float4*)x, (const float4*)(ln2g + l * D_),
                                 (const float4*)(ln2b + l * D_), (float4*)xn,
                                 (__half2*)ah);

        // h = relu(xn @ w1 + b1)  -> fp16 directly
        mma_gemm_k<true,false,true,true><<<dim3(M_/128, DFF_/256), blk, SMTOT_>>>(
            M_, DFF_, D_, ah, wh + o1,
            b1 + (size_t)l * DFF_, nullptr, nullptr,
            (__half2*)hh, 0, 0);

        // x = xn + h @ w2 + b2
        mma_gemm_k<true,true,false,false><<<dim3(M_/128, D_/256), blk, SMTOT_>>>(
            M_, D_, DFF_, hh, wh + o2,
            b2 + l * D_, xn, x, nullptr, 0, 0);
    }

    layernorm_k<<<M_, blk>>>((const float4*)x, (const float4*)lnfg,
                             (const float4*)lnfb, (float4*)xn,
                             (__half2*)ah);

    // logits = xn @ w_head + b_head
    mma_gemm_k<true,false,false,false><<<dim3(M_/128, V_/256), blk, SMTOT_>>>(
        M_, V_, D_, ah, wh + WH_OFF_,
        bhead, nullptr, out, nullptr, 0, 0);
}

// round 10
// speedup vs baseline: 2.4784x; 2.0095x over previous
#include <cuda_runtime.h>
#include <cuda_fp16.h>
#include <cstdint>
#include <math.h>

// ---------------------------------------------------------------------------
// MinGPT forward.  B=4, S=1024, D=1024, H=16, HS=64, L=4, DFF=4096, V=32000.
// Round 10: tensor-core two-pass attention (fp16 QK^T + PV via mma.sync,
// fp32 softmax) + single-product fp16 GEMM (R9).
// ---------------------------------------------------------------------------

#define B_  4
#define S_  1024
#define D_  1024
#define H_  16
#define HS_ 64
#define L_  4
#define DFF_ 4096
#define V_  32000
#define M_  (B_ * S_)
#define MD_ ((size_t)M_ * D_)
#define EPS_ 1e-5f
#define SCALE_ 0.03125f        // D^-0.5 = 1/32 (reference uses d_model)

// ------------------------- scratch -----------------------------------------
__device__ float g_x  [M_ * D_];
__device__ float g_xn [M_ * D_];

__device__ __align__(16) __half g_qkvh[3 * M_ * D_];
__device__ __align__(16) __half g_ah[M_ * D_];
__device__ __align__(16) __half g_hh[M_ * DFF_];

#define DD_      ((size_t)D_ * D_)
#define WQ_OFF_  ((size_t)0)
#define WK_OFF_  (4 * DD_)
#define WV_OFF_  (8 * DD_)
#define WO_OFF_  (12 * DD_)
#define W1_OFF_  (16 * DD_)
#define W2_OFF_  (32 * DD_)
#define WH_OFF_  (48 * DD_)
#define WT_TOT_  (48 * DD_ + (size_t)D_ * V_)
__device__ __align__(16) __half g_wh[WT_TOT_];

// ------------------------- PTX helpers --------------------------------------
__device__ __forceinline__ uint32_t smem_u32(const void* p) {
    uint32_t a;
    asm("{ .reg .u64 t; cvta.to.shared.u64 t, %1; cvt.u32.u64 %0, t; }"
        : "=r"(a) : "l"(p));
    return a;
}
#define CP16(dst, src) \
    asm volatile("cp.async.cg.shared.global [%0], [%1], 16;" :: "r"(dst), "l"(src))
#define CPCOMMIT() asm volatile("cp.async.commit_group;" ::: "memory")
#define CPWAIT0()  asm volatile("cp.async.wait_group 0;" ::: "memory")
#define CPWAIT1()  asm volatile("cp.async.wait_group 1;" ::: "memory")

__device__ __forceinline__ void ldsm4(uint32_t* r, uint32_t addr) {
    asm volatile("ldmatrix.sync.aligned.m8n8.x4.shared.b16 {%0,%1,%2,%3}, [%4];"
        : "=r"(r[0]), "=r"(r[1]), "=r"(r[2]), "=r"(r[3]) : "r"(addr));
}
__device__ __forceinline__ void ldsm4t(uint32_t* r, uint32_t addr) {
    asm volatile("ldmatrix.sync.aligned.m8n8.x4.trans.shared.b16 {%0,%1,%2,%3}, [%4];"
        : "=r"(r[0]), "=r"(r[1]), "=r"(r[2]), "=r"(r[3]) : "r"(addr));
}
__device__ __forceinline__ void ldsm2(uint32_t* r, uint32_t addr) {
    asm volatile("ldmatrix.sync.aligned.m8n8.x2.shared.b16 {%0,%1}, [%2];"
        : "=r"(r[0]), "=r"(r[1]) : "r"(addr));
}
__device__ __forceinline__ void ldsm2t(uint32_t* r, uint32_t addr) {
    asm volatile("ldmatrix.sync.aligned.m8n8.x2.trans.shared.b16 {%0,%1}, [%2];"
        : "=r"(r[0]), "=r"(r[1]) : "r"(addr));
}
__device__ __forceinline__ void mma16816(float* d, const uint32_t* a, const uint32_t* b) {
    asm volatile(
        "mma.sync.aligned.m16n8k16.row.col.f32.f16.f16.f32 "
        "{%0,%1,%2,%3}, {%4,%5,%6,%7}, {%8,%9}, {%0,%1,%2,%3};"
        : "+f"(d[0]), "+f"(d[1]), "+f"(d[2]), "+f"(d[3])
        : "r"(a[0]), "r"(a[1]), "r"(a[2]), "r"(a[3]), "r"(b[0]), "r"(b[1]));
}

// ------------------------- embedding ----------------------------------------
__global__ __launch_bounds__(256) void embed_k(
    const int* __restrict__ idx, const float4* __restrict__ tok,
    const float4* __restrict__ pos, float4* __restrict__ x)
{
    int row = blockIdx.x;
    int s   = row & (S_ - 1);
    int t   = idx[row];
    int c   = threadIdx.x;
    float4 tv = tok[(size_t)t * (D_ / 4) + c];
    float4 pv = pos[(size_t)s * (D_ / 4) + c];
    float4 o;
    o.x = tv.x + pv.x; o.y = tv.y + pv.y; o.z = tv.z + pv.z; o.w = tv.w + pv.w;
    x[(size_t)row * (D_ / 4) + c] = o;
}

// ------------------------- layer norm + fused fp16 convert -------------------
__global__ __launch_bounds__(256) void layernorm_k(
    const float4* __restrict__ x, const float4* __restrict__ g,
    const float4* __restrict__ bb, float4* __restrict__ y,
    __half2* __restrict__ oh)
{
    int row = blockIdx.x;
    int tid = threadIdx.x;
    __shared__ float red[256];

    float4 xv = x[(size_t)row * 256 + tid];
    float s = xv.x + xv.y + xv.z + xv.w;
    red[tid] = s; __syncthreads();
    #pragma unroll
    for (int st = 128; st > 0; st >>= 1) {
        if (tid < st) red[tid] += red[tid + st];
        __syncthreads();
    }
    float mu = red[0] * (1.0f / D_);
    __syncthreads();

    float dx = xv.x - mu, dy = xv.y - mu, dz = xv.z - mu, dw = xv.w - mu;
    float s2 = dx * dx + dy * dy + dz * dz + dw * dw;
    red[tid] = s2; __syncthreads();
    #pragma unroll
    for (int st = 128; st > 0; st >>= 1) {
        if (tid < st) red[tid] += red[tid + st];
        __syncthreads();
    }
    float inv = rsqrtf(red[0] * (1.0f / D_) + EPS_);

    float4 gv = g[tid], bv = bb[tid];
    float4 o;
    o.x = dx * inv * gv.x + bv.x;
    o.y = dy * inv * gv.y + bv.y;
    o.z = dz * inv * gv.z + bv.z;
    o.w = dw * inv * gv.w + bv.w;
    size_t i = (size_t)row * 256 + tid;
    y[i] = o;

    oh[2 * i]     = __halves2half2(__float2half_rn(o.x), __float2half_rn(o.y));
    oh[2 * i + 1] = __halves2half2(__float2half_rn(o.z), __float2half_rn(o.w));
}

// ------------------------- fp32 -> fp16 (weights) ----------------------------
__global__ __launch_bounds__(256) void wsplit_k(
    const float4* __restrict__ x, __half2* __restrict__ h, int n4)
{
    int i = blockIdx.x * 256 + threadIdx.x;
    if (i >= n4) return;
    float4 v = x[i];
    h[2 * i]     = __halves2half2(__float2half_rn(v.x), __float2half_rn(v.y));
    h[2 * i + 1] = __halves2half2(__float2half_rn(v.z), __float2half_rn(v.w));
}

// ------------------------- mma.sync GEMM ------------------------------------
#define ATILEB_ 16384
#define BTILEB_ 32768
#define BUFB_   (ATILEB_ + BTILEB_)
#define SMTOT_  (2 * BUFB_)

template<bool BIAS, bool RES, bool RELU, bool OHALF>
__global__ __launch_bounds__(256, 1) void mma_gemm_k(
    int M, int N, int K,
    const __half* __restrict__ Ah,
    const __half* __restrict__ Bw,
    const float* __restrict__ bias, const float* __restrict__ res,
    float* __restrict__ C,
    __half2* __restrict__ Oh,
    size_t bzS, size_t czS, size_t ozS)
{
    extern __shared__ char smem[];
    const uint32_t sb = smem_u32(smem);
    const int tid = threadIdx.x, wid = tid >> 5, lane = tid & 31;
    const int mb = blockIdx.x, nb = blockIdx.y;
    Bw += blockIdx.z * bzS;
    C  += blockIdx.z * czS;
    if (OHALF) Oh += blockIdx.z * ozS;
    const size_t ar0 = (size_t)mb * 128, bc0 = (size_t)nb * 256;
    const int wm = (wid >> 2) * 64, wn = (wid & 3) * 64;

    float acc[4][8][4];
    #pragma unroll
    for (int i = 0; i < 4; i++)
        #pragma unroll
        for (int j = 0; j < 8; j++)
            #pragma unroll
            for (int e = 0; e < 4; e++) acc[i][j][e] = 0.0f;

    const int nch = K >> 6;

    auto fill = [&](int buf, int c) {
        const size_t kof = (size_t)c << 6;
        const uint32_t bb = sb + buf * BUFB_;
        #pragma unroll
        for (int i = 0; i < 4; i++) {
            int id = tid + 256 * i;
            int r  = id >> 3;
            int cx = id & 7;
            uint32_t so = (uint32_t)(r * 128 + cx * 16);
            so ^= (so >> 3) & 0x70;
            size_t ai = (ar0 + r) * (size_t)K + kof + cx * 8;
            CP16(bb + so, Ah + ai);
        }
        #pragma unroll
        for (int i = 0; i < 8; i++) {
            int id = tid + 256 * i;
            int kr = id >> 5;
            int cx = id & 31;
            uint32_t so = (uint32_t)(kr * 512 + ((cx ^ (kr & 31)) * 16));
            size_t bi = (kof + kr) * (size_t)N + bc0 + cx * 8;
            CP16(bb + ATILEB_ + so, Bw + bi);
        }
    };

    fill(0, 0); CPCOMMIT();

    uint32_t fa[4][4], fb[8][2];
    const int arow = wm + (lane & 15);
    const int akb  = (lane >> 4) * 16;
    const int krl  = lane & 15;
    const int nsel = lane >> 4;

    for (int c = 0; c < nch; c++) {
        if (c + 1 < nch) { fill((c + 1) & 1, c + 1); CPCOMMIT(); CPWAIT1(); }
        else             { CPWAIT0(); }
        __syncthreads();

        const uint32_t base = sb + (c & 1) * BUFB_;
        #pragma unroll
        for (int ks = 0; ks < 4; ks++) {
            #pragma unroll
            for (int i = 0; i < 4; i++) {
                uint32_t so = (uint32_t)((arow + i * 16) * 128 + ks * 32 + akb);
                so ^= (so >> 3) & 0x70;
                ldsm4(fa[i], base + so);
            }
            const uint32_t krow = (uint32_t)(ks * 16 + krl);
            #pragma unroll
            for (int j2 = 0; j2 < 4; j2++) {
                uint32_t cx = (uint32_t)((wn >> 3) + 2 * j2 + nsel);
                uint32_t so = krow * 512 + ((cx ^ (krow & 31)) * 16);
                uint32_t r[4];
                ldsm4t(r, base + ATILEB_ + so);
                fb[2 * j2 + 0][0] = r[0]; fb[2 * j2 + 0][1] = r[1];
                fb[2 * j2 + 1][0] = r[2]; fb[2 * j2 + 1][1] = r[3];
            }
            #pragma unroll
            for (int i = 0; i < 4; i++)
                #pragma unroll
                for (int j = 0; j < 8; j++)
                    mma16816(acc[i][j], fa[i], fb[j]);
        }
        __syncthreads();
    }

    const int g  = lane >> 2, tg = lane & 3;
    const size_t row0 = ar0 + wm, col0 = bc0 + wn;
    #pragma unroll
    for (int i = 0; i < 4; i++) {
        #pragma unroll
        for (int j = 0; j < 8; j++) {
            size_t col = col0 + j * 8 + tg * 2;
            float bx = 0.0f, by = 0.0f;
            if (BIAS) { bx = bias[col]; by = bias[col + 1]; }
            #pragma unroll
            for (int half = 0; half < 2; half++) {
                size_t row = row0 + i * 16 + g + half * 8;
                float vx = acc[i][j][2 * half + 0] + bx;
                float vy = acc[i][j][2 * half + 1] + by;
                size_t gi = row * (size_t)N + col;
                if (RES) { vx += res[gi]; vy += res[gi + 1]; }
                if (RELU) { vx = fmaxf(vx, 0.0f); vy = fmaxf(vy, 0.0f); }
                if (OHALF) {
                    Oh[gi >> 1] = __halves2half2(__float2half_rn(vx),
                                                 __float2half_rn(vy));
                } else {
                    float2 o; o.x = vx; o.y = vy;
                    *(float2*)(C + gi) = o;
                }
            }
        }
    }
}

// ------------------------- tensor-core attention -----------------------------
// Block: 16 queries x 1 head.  Pass A: S = Q K^T (mma, fp32 acc) -> S fp32.
// Softmax fp32 -> P fp16 (swizzled).  Pass B: O = P V (mma) -> ah fp16.
#define QT_    16
#define NTL_   128
#define SROW_  1032
#define SBY_   (QT_ * SROW_ * 4)           // 66048
#define P_OFF_ SBY_                        // 66048 (fp16, rows 2048B)
#define Q_OFF_ (P_OFF_ + QT_ * 2048)       // 98816
#define KV_OFF_ (Q_OFF_ + 2048)            // 100864
#define KVB_   16384
#define RINV_OFF_ (KV_OFF_ + 2 * KVB_)     // 133632
#define ATT_SM_ (RINV_OFF_ + 64)           // 133696

__global__ __launch_bounds__(256, 1) void attn_tc_k(
    const __half* __restrict__ qkvh, __half* __restrict__ oh)
{
    extern __shared__ char smc[];
    const uint32_t sb = smem_u32(smc);
    float* S    = (float*)smc;
    float* Rinv = (float*)(smc + RINV_OFF_);

    const int tid = threadIdx.x, wid = tid >> 5, lane = tid & 31;
    const int qt = blockIdx.x, h = blockIdx.y, b = blockIdx.z;
    const int q0 = qt * QT_;
    const int nt = (q0 + QT_ + NTL_ - 1) / NTL_;   // j tiles (128 each)

    const size_t hrow = (size_t)H_ * HS_;          // 1024 halves per token row
    const __half* qg = qkvh + ((size_t)b * S_ + q0) * hrow + h * HS_;
    const __half* kg = qkvh + MD_     + (size_t)b * S_ * hrow + h * HS_;
    const __half* vg = qkvh + 2 * MD_ + (size_t)b * S_ * hrow + h * HS_;

    auto stageKV = [&](uint32_t dst, const __half* src, int t) {
        int j0 = t * NTL_;
        #pragma unroll
        for (int i = 0; i < 4; i++) {
            int id = tid + 256 * i;          // 0..1023
            int r  = id >> 3;
            int cx = id & 7;
            uint32_t so = (uint32_t)(r * 128 + cx * 16);
            so ^= (so >> 3) & 0x70;
            CP16(dst + so, src + (size_t)(j0 + r) * hrow + cx * 8);
        }
    };

    // ---- load Q tile (group) then K tile 0 (group) ----
    if (tid < 128) {
        int r = tid >> 3, cx = tid & 7;
        uint32_t so = (uint32_t)(r * 128 + cx * 16);
        so ^= (so >> 3) & 0x70;
        CP16(sb + Q_OFF_ + so, qg + (size_t)r * hrow + cx * 8);
    }
    CPCOMMIT();
    stageKV(sb + KV_OFF_, kg, 0); CPCOMMIT();
    CPWAIT1();                 // Q done
    __syncthreads();

    // Q fragments, register resident for the whole kernel
    uint32_t qf[4][4];
    {
        const int arow = lane & 15;
        const int akb  = (lane >> 4) * 16;
        #pragma unroll
        for (int ks = 0; ks < 4; ks++) {
            uint32_t so = (uint32_t)(arow * 128 + ks * 32 + akb);
            so ^= (so >> 3) & 0x70;
            ldsm4(qf[ks], sb + Q_OFF_ + so);
        }
    }

    // ---- pass A: scores ----
    for (int t = 0; t < nt; t++) {
        if (t + 1 < nt) { stageKV(sb + KV_OFF_ + ((t + 1) & 1) * KVB_, kg, t + 1); CPCOMMIT(); CPWAIT1(); }
        else            { CPWAIT0(); }
        __syncthreads();

        const uint32_t kb = sb + KV_OFF_ + (t & 1) * KVB_;
        #pragma unroll
        for (int sub = 0; sub < 2; sub++) {
            int n0 = (2 * wid + sub) * 8;
            float acc[4] = {0.0f, 0.0f, 0.0f, 0.0f};
            #pragma unroll
            for (int ks = 0; ks < 4; ks++) {
                uint32_t bf[2];
                uint32_t so = (uint32_t)((n0 + (lane & 7)) * 128 + ks * 32 + ((lane >> 3) & 1) * 16);
                so ^= (so >> 3) & 0x70;
                ldsm2(bf, kb + so);
                mma16816(acc, qf[ks], bf);
            }
            int g = lane >> 2, tg = lane & 3;
            int col = t * NTL_ + n0 + tg * 2;
            S[g * SROW_ + col]           = acc[0] * SCALE_;
            S[g * SROW_ + col + 1]       = acc[1] * SCALE_;
            S[(g + 8) * SROW_ + col]     = acc[2] * SCALE_;
            S[(g + 8) * SROW_ + col + 1] = acc[3] * SCALE_;
        }
        __syncthreads();
    }

    // ---- softmax (fp32) -> P fp16, swizzled ----
    {
        const int jmax = nt * NTL_;
        __half* P = (__half*)(smc + P_OFF_);
        #pragma unroll
        for (int qq = 0; qq < 2; qq++) {
            int r  = 2 * wid + qq;
            int nq = q0 + r + 1;
            float m = -1e30f;
            for (int j = lane; j < nq; j += 32) m = fmaxf(m, S[r * SROW_ + j]);
            #pragma unroll
            for (int st = 16; st > 0; st >>= 1)
                m = fmaxf(m, __shfl_xor_sync(0xffffffff, m, st));
            float sum = 0.0f;
            for (int j = lane; j < jmax; j += 32) {
                float e = 0.0f;
                if (j < nq) { e = __expf(S[r * SROW_ + j] - m); sum += e; }
                int ch = j >> 3;
                uint32_t off = (uint32_t)(r * 2048 + ((ch ^ (r & 7)) * 16) + (j & 7) * 2);
                *(__half*)((char*)P + off) = __float2half_rn(e);
            }
            #pragma unroll
            for (int st = 16; st > 0; st >>= 1)
                sum += __shfl_xor_sync(0xffffffff, sum, st);
            if (lane == 0) Rinv[r] = 1.0f / sum;
        }
    }
    __syncthreads();

    // ---- pass B: O = P @ V ----
    float oacc[4] = {0.0f, 0.0f, 0.0f, 0.0f};
    stageKV(sb + KV_OFF_, vg, 0); CPCOMMIT();
    for (int t = 0; t < nt; t++) {
        if (t + 1 < nt) { stageKV(sb + KV_OFF_ + ((t + 1) & 1) * KVB_, vg, t + 1); CPCOMMIT(); CPWAIT1(); }
        else            { CPWAIT0(); }
        __syncthreads();

        const uint32_t vb = sb + KV_OFF_ + (t & 1) * KVB_;
        #pragma unroll
        for (int ks = 0; ks < 8; ks++) {
            uint32_t pf[4];
            {
                int r  = lane & 15;
                int ch = t * 16 + 2 * ks + (lane >> 4);
                uint32_t addr = (uint32_t)(P_OFF_ + r * 2048 + ((ch ^ (r & 7)) * 16));
                ldsm4(pf, sb + addr);
            }
            uint32_t vf[2];
            {
                int kr = ks * 16 + (lane & 15);
                int cx = wid;                       // d-chunk for this warp
                uint32_t so = (uint32_t)(kr * 128 + ((cx ^ (kr & 7)) * 16));
                ldsm2t(vf, vb + so);
            }
            mma16816(oacc, pf, vf);
        }
        __syncthreads();
    }

    // ---- epilogue ----
    {
        int g = lane >> 2, tg = lane & 3;
        int col = wid * 8 + tg * 2;
        #pragma unroll
        for (int half = 0; half < 2; half++) {
            int row = g + half * 8;
            float rv = Rinv[row];
            __half2 o = __halves2half2(__float2half_rn(oacc[2 * half + 0] * rv),
                                       __float2half_rn(oacc[2 * half + 1] * rv));
            *(__half2*)(oh + ((size_t)b * S_ + q0 + row) * hrow + h * HS_ + col) = o;
        }
    }
}

// ------------------------- driver -------------------------------------------
extern "C" void kernel_launch(void* const* d_in, const int* in_sizes, int n_in,
                              void* d_out, int out_size)
{
    const int*   idx   = (const int*)  d_in[0];
    const float* tok   = (const float*)d_in[1];
    const float* pos   = (const float*)d_in[2];
    const float* ln1g  = (const float*)d_in[3];
    const float* ln1b  = (const float*)d_in[4];
    const float* ln2g  = (const float*)d_in[5];
    const float* ln2b  = (const float*)d_in[6];
    const float* wq    = (const float*)d_in[7];
    const float* wk    = (const float*)d_in[8];
    const float* wv    = (const float*)d_in[9];
    const float* wo    = (const float*)d_in[10];
    const float* bo    = (const float*)d_in[11];
    const float* w1    = (const float*)d_in[12];
    const float* b1    = (const float*)d_in[13];
    const float* w2    = (const float*)d_in[14];
    const float* b2    = (const float*)d_in[15];
    const float* lnfg  = (const float*)d_in[16];
    const float* lnfb  = (const float*)d_in[17];
    const float* whead = (const float*)d_in[18];
    const float* bhead = (const float*)d_in[19];
    float* out = (float*)d_out;

    float *x, *xn;
    __half *qkvh, *ah, *hh, *wh;
    cudaGetSymbolAddress((void**)&x,    g_x);
    cudaGetSymbolAddress((void**)&xn,   g_xn);
    cudaGetSymbolAddress((void**)&qkvh, g_qkvh);
    cudaGetSymbolAddress((void**)&ah,   g_ah);
    cudaGetSymbolAddress((void**)&hh,   g_hh);
    cudaGetSymbolAddress((void**)&wh,   g_wh);

    cudaFuncSetAttribute(mma_gemm_k<false,false,false,true>,  cudaFuncAttributeMaxDynamicSharedMemorySize, SMTOT_);
    cudaFuncSetAttribute(mma_gemm_k<true,true,false,false>,   cudaFuncAttributeMaxDynamicSharedMemorySize, SMTOT_);
    cudaFuncSetAttribute(mma_gemm_k<true,false,true,true>,    cudaFuncAttributeMaxDynamicSharedMemorySize, SMTOT_);
    cudaFuncSetAttribute(mma_gemm_k<true,false,false,false>,  cudaFuncAttributeMaxDynamicSharedMemorySize, SMTOT_);
    cudaFuncSetAttribute(attn_tc_k, cudaFuncAttributeMaxDynamicSharedMemorySize, ATT_SM_);

    dim3 blk(256);

    // ---- weight fp16 conversion ----
    {
        int nQ = (int)(4 * DD_ / 4);
        int nF = (int)(16 * DD_ / 4);
        int nH = (int)((size_t)D_ * V_ / 4);
        wsplit_k<<<(nQ + 255)/256, blk>>>((const float4*)wq, (__half2*)(wh + WQ_OFF_), nQ);
        wsplit_k<<<(nQ + 255)/256, blk>>>((const float4*)wk, (__half2*)(wh + WK_OFF_), nQ);
        wsplit_k<<<(nQ + 255)/256, blk>>>((const float4*)wv, (__half2*)(wh + WV_OFF_), nQ);
        wsplit_k<<<(nQ + 255)/256, blk>>>((const float4*)wo, (__half2*)(wh + WO_OFF_), nQ);
        wsplit_k<<<(nF + 255)/256, blk>>>((const float4*)w1, (__half2*)(wh + W1_OFF_), nF);
        wsplit_k<<<(nF + 255)/256, blk>>>((const float4*)w2, (__half2*)(wh + W2_OFF_), nF);
        wsplit_k<<<(nH + 255)/256, blk>>>((const float4*)whead, (__half2*)(wh + WH_OFF_), nH);
    }

    embed_k<<<M_, blk>>>(idx, (const float4*)tok, (const float4*)pos, (float4*)x);

    for (int l = 0; l < L_; l++) {
        size_t oq = WQ_OFF_ + (size_t)l * DD_;
        size_t oo = WO_OFF_ + (size_t)l * DD_;
        size_t o1 = W1_OFF_ + (size_t)l * 4 * DD_;
        size_t o2 = W2_OFF_ + (size_t)l * 4 * DD_;

        layernorm_k<<<M_, blk>>>((const float4*)x, (const float4*)(ln1g + l * D_),
                                 (const float4*)(ln1b + l * D_), (float4*)xn,
                                 (__half2*)ah);

        // fused QKV -> fp16 qkv slabs
        mma_gemm_k<false,false,false,true><<<dim3(M_/128, D_/256, 3), blk, SMTOT_>>>(
            M_, D_, D_, ah, wh + oq, nullptr, nullptr, nullptr,
            (__half2*)qkvh, 4 * DD_, 0, MD_ / 2);

        attn_tc_k<<<dim3(S_ / QT_, H_, B_), 256, ATT_SM_>>>(qkvh, ah);

        // x = xn + att @ wo + bo
        mma_gemm_k<true,true,false,false><<<dim3(M_/128, D_/256), blk, SMTOT_>>>(
            M_, D_, D_, ah, wh + oo, bo + l * D_, xn, x,
            nullptr, 0, 0, 0);

        layernorm_k<<<M_, blk>>>((const float4*)x, (const float4*)(ln2g + l * D_),
                                 (const float4*)(ln2b + l * D_), (float4*)xn,
                                 (__half2*)ah);

        // h = relu(xn @ w1 + b1)  -> fp16 directly
        mma_gemm_k<true,false,true,true><<<dim3(M_/128, DFF_/256), blk, SMTOT_>>>(
            M_, DFF_, D_, ah, wh + o1,
            b1 + (size_t)l * DFF_, nullptr, nullptr,
            (__half2*)hh, 0, 0, 0);

        // x = xn + h @ w2 + b2
        mma_gemm_k<true,true,false,false><<<dim3(M_/128, D_/256), blk, SMTOT_>>>(
            M_, D_, DFF_, hh, wh + o2,
            b2 + l * D_, xn, x, nullptr, 0, 0, 0);
    }

    layernorm_k<<<M_, blk>>>((const float4*)x, (const float4*)lnfg,
                             (const float4*)lnfb, (float4*)xn,
                             (__half2*)ah);

    // logits = xn @ w_head + b_head
    mma_gemm_k<true,false,false,false><<<dim3(M_/128, V_/256), blk, SMTOT_>>>(
        M_, V_, D_, ah, wh + WH_OFF_,
        bhead, nullptr, out, nullptr, 0, 0, 0);
}

// round 11
// speedup vs baseline: 2.4860x; 1.0031x over previous
#include <cuda_runtime.h>
#include <cuda_fp16.h>
#include <cstdint>
#include <math.h>

// ---------------------------------------------------------------------------
// MinGPT forward.  B=4, S=1024, D=1024, H=16, HS=64, L=4, DFF=4096, V=32000.
// Round 11: 3-stage cp.async GEMM pipeline + heavy-first attention
// scheduling + MLP=2 weight conversion.  (GEMM numerics = R9/R10.)
// ---------------------------------------------------------------------------

#define B_  4
#define S_  1024
#define D_  1024
#define H_  16
#define HS_ 64
#define L_  4
#define DFF_ 4096
#define V_  32000
#define M_  (B_ * S_)
#define MD_ ((size_t)M_ * D_)
#define EPS_ 1e-5f
#define SCALE_ 0.03125f        // D^-0.5 = 1/32 (reference uses d_model)

// ------------------------- scratch -----------------------------------------
__device__ float g_x  [M_ * D_];
__device__ float g_xn [M_ * D_];

__device__ __align__(16) __half g_qkvh[3 * M_ * D_];
__device__ __align__(16) __half g_ah[M_ * D_];
__device__ __align__(16) __half g_hh[M_ * DFF_];

#define DD_      ((size_t)D_ * D_)
#define WQ_OFF_  ((size_t)0)
#define WK_OFF_  (4 * DD_)
#define WV_OFF_  (8 * DD_)
#define WO_OFF_  (12 * DD_)
#define W1_OFF_  (16 * DD_)
#define W2_OFF_  (32 * DD_)
#define WH_OFF_  (48 * DD_)
#define WT_TOT_  (48 * DD_ + (size_t)D_ * V_)
__device__ __align__(16) __half g_wh[WT_TOT_];

// ------------------------- PTX helpers --------------------------------------
__device__ __forceinline__ uint32_t smem_u32(const void* p) {
    uint32_t a;
    asm("{ .reg .u64 t; cvta.to.shared.u64 t, %1; cvt.u32.u64 %0, t; }"
        : "=r"(a) : "l"(p));
    return a;
}
#define CP16(dst, src) \
    asm volatile("cp.async.cg.shared.global [%0], [%1], 16;" :: "r"(dst), "l"(src))
#define CPCOMMIT() asm volatile("cp.async.commit_group;" ::: "memory")
#define CPWAIT0()  asm volatile("cp.async.wait_group 0;" ::: "memory")
#define CPWAIT1()  asm volatile("cp.async.wait_group 1;" ::: "memory")
#define CPWAIT2()  asm volatile("cp.async.wait_group 2;" ::: "memory")

__device__ __forceinline__ void ldsm4(uint32_t* r, uint32_t addr) {
    asm volatile("ldmatrix.sync.aligned.m8n8.x4.shared.b16 {%0,%1,%2,%3}, [%4];"
        : "=r"(r[0]), "=r"(r[1]), "=r"(r[2]), "=r"(r[3]) : "r"(addr));
}
__device__ __forceinline__ void ldsm4t(uint32_t* r, uint32_t addr) {
    asm volatile("ldmatrix.sync.aligned.m8n8.x4.trans.shared.b16 {%0,%1,%2,%3}, [%4];"
        : "=r"(r[0]), "=r"(r[1]), "=r"(r[2]), "=r"(r[3]) : "r"(addr));
}
__device__ __forceinline__ void ldsm2(uint32_t* r, uint32_t addr) {
    asm volatile("ldmatrix.sync.aligned.m8n8.x2.shared.b16 {%0,%1}, [%2];"
        : "=r"(r[0]), "=r"(r[1]) : "r"(addr));
}
__device__ __forceinline__ void ldsm2t(uint32_t* r, uint32_t addr) {
    asm volatile("ldmatrix.sync.aligned.m8n8.x2.trans.shared.b16 {%0,%1}, [%2];"
        : "=r"(r[0]), "=r"(r[1]) : "r"(addr));
}
__device__ __forceinline__ void mma16816(float* d, const uint32_t* a, const uint32_t* b) {
    asm volatile(
        "mma.sync.aligned.m16n8k16.row.col.f32.f16.f16.f32 "
        "{%0,%1,%2,%3}, {%4,%5,%6,%7}, {%8,%9}, {%0,%1,%2,%3};"
        : "+f"(d[0]), "+f"(d[1]), "+f"(d[2]), "+f"(d[3])
        : "r"(a[0]), "r"(a[1]), "r"(a[2]), "r"(a[3]), "r"(b[0]), "r"(b[1]));
}

// ------------------------- embedding ----------------------------------------
__global__ __launch_bounds__(256) void embed_k(
    const int* __restrict__ idx, const float4* __restrict__ tok,
    const float4* __restrict__ pos, float4* __restrict__ x)
{
    int row = blockIdx.x;
    int s   = row & (S_ - 1);
    int t   = idx[row];
    int c   = threadIdx.x;
    float4 tv = tok[(size_t)t * (D_ / 4) + c];
    float4 pv = pos[(size_t)s * (D_ / 4) + c];
    float4 o;
    o.x = tv.x + pv.x; o.y = tv.y + pv.y; o.z = tv.z + pv.z; o.w = tv.w + pv.w;
    x[(size_t)row * (D_ / 4) + c] = o;
}

// ------------------------- layer norm + fused fp16 convert -------------------
__global__ __launch_bounds__(256) void layernorm_k(
    const float4* __restrict__ x, const float4* __restrict__ g,
    const float4* __restrict__ bb, float4* __restrict__ y,
    __half2* __restrict__ oh)
{
    int row = blockIdx.x;
    int tid = threadIdx.x;
    __shared__ float red[256];

    float4 xv = x[(size_t)row * 256 + tid];
    float s = xv.x + xv.y + xv.z + xv.w;
    red[tid] = s; __syncthreads();
    #pragma unroll
    for (int st = 128; st > 0; st >>= 1) {
        if (tid < st) red[tid] += red[tid + st];
        __syncthreads();
    }
    float mu = red[0] * (1.0f / D_);
    __syncthreads();

    float dx = xv.x - mu, dy = xv.y - mu, dz = xv.z - mu, dw = xv.w - mu;
    float s2 = dx * dx + dy * dy + dz * dz + dw * dw;
    red[tid] = s2; __syncthreads();
    #pragma unroll
    for (int st = 128; st > 0; st >>= 1) {
        if (tid < st) red[tid] += red[tid + st];
        __syncthreads();
    }
    float inv = rsqrtf(red[0] * (1.0f / D_) + EPS_);

    float4 gv = g[tid], bv = bb[tid];
    float4 o;
    o.x = dx * inv * gv.x + bv.x;
    o.y = dy * inv * gv.y + bv.y;
    o.z = dz * inv * gv.z + bv.z;
    o.w = dw * inv * gv.w + bv.w;
    size_t i = (size_t)row * 256 + tid;
    y[i] = o;

    oh[2 * i]     = __halves2half2(__float2half_rn(o.x), __float2half_rn(o.y));
    oh[2 * i + 1] = __halves2half2(__float2half_rn(o.z), __float2half_rn(o.w));
}

// ------------------------- fp32 -> fp16 (weights), MLP=2 ---------------------
__global__ __launch_bounds__(256) void wsplit_k(
    const float4* __restrict__ x, __half2* __restrict__ h, int n4)
{
    int half = n4 >> 1;
    int i = blockIdx.x * 256 + threadIdx.x;
    if (i >= half) return;
    float4 v0 = x[i];
    float4 v1 = x[i + half];
    h[2 * i]     = __halves2half2(__float2half_rn(v0.x), __float2half_rn(v0.y));
    h[2 * i + 1] = __halves2half2(__float2half_rn(v0.z), __float2half_rn(v0.w));
    h[2 * (i + half)]     = __halves2half2(__float2half_rn(v1.x), __float2half_rn(v1.y));
    h[2 * (i + half) + 1] = __halves2half2(__float2half_rn(v1.z), __float2half_rn(v1.w));
}

// ------------------------- mma.sync GEMM (3-stage pipeline) ------------------
#define ATILEB_ 16384
#define BTILEB_ 32768
#define BUFB_   (ATILEB_ + BTILEB_)        // 48 KB
#define SMTOT_  (3 * BUFB_)                // 144 KB

template<bool BIAS, bool RES, bool RELU, bool OHALF>
__global__ __launch_bounds__(256, 1) void mma_gemm_k(
    int M, int N, int K,
    const __half* __restrict__ Ah,
    const __half* __restrict__ Bw,
    const float* __restrict__ bias, const float* __restrict__ res,
    float* __restrict__ C,
    __half2* __restrict__ Oh,
    size_t bzS, size_t czS, size_t ozS)
{
    extern __shared__ char smem[];
    const uint32_t sb = smem_u32(smem);
    const int tid = threadIdx.x, wid = tid >> 5, lane = tid & 31;
    const int mb = blockIdx.x, nb = blockIdx.y;
    Bw += blockIdx.z * bzS;
    C  += blockIdx.z * czS;
    if (OHALF) Oh += blockIdx.z * ozS;
    const size_t ar0 = (size_t)mb * 128, bc0 = (size_t)nb * 256;
    const int wm = (wid >> 2) * 64, wn = (wid & 3) * 64;

    float acc[4][8][4];
    #pragma unroll
    for (int i = 0; i < 4; i++)
        #pragma unroll
        for (int j = 0; j < 8; j++)
            #pragma unroll
            for (int e = 0; e < 4; e++) acc[i][j][e] = 0.0f;

    const int nch = K >> 6;

    auto fill = [&](int buf, int c) {
        const size_t kof = (size_t)c << 6;
        const uint32_t bb = sb + buf * BUFB_;
        #pragma unroll
        for (int i = 0; i < 4; i++) {
            int id = tid + 256 * i;
            int r  = id >> 3;
            int cx = id & 7;
            uint32_t so = (uint32_t)(r * 128 + cx * 16);
            so ^= (so >> 3) & 0x70;
            size_t ai = (ar0 + r) * (size_t)K + kof + cx * 8;
            CP16(bb + so, Ah + ai);
        }
        #pragma unroll
        for (int i = 0; i < 8; i++) {
            int id = tid + 256 * i;
            int kr = id >> 5;
            int cx = id & 31;
            uint32_t so = (uint32_t)(kr * 512 + ((cx ^ (kr & 31)) * 16));
            size_t bi = (kof + kr) * (size_t)N + bc0 + cx * 8;
            CP16(bb + ATILEB_ + so, Bw + bi);
        }
    };

    fill(0, 0); CPCOMMIT();
    fill(1, 1); CPCOMMIT();

    uint32_t fa[4][4], fb[8][2];
    const int arow = wm + (lane & 15);
    const int akb  = (lane >> 4) * 16;
    const int krl  = lane & 15;
    const int nsel = lane >> 4;

    int buf = 0;
    for (int c = 0; c < nch; c++) {
        if (c + 2 < nch) {
            int nbuf = buf + 2; if (nbuf >= 3) nbuf -= 3;
            fill(nbuf, c + 2); CPCOMMIT(); CPWAIT2();
        } else if (c + 1 < nch) { CPWAIT1(); }
        else                    { CPWAIT0(); }
        __syncthreads();

        const uint32_t base = sb + buf * BUFB_;
        #pragma unroll
        for (int ks = 0; ks < 4; ks++) {
            #pragma unroll
            for (int i = 0; i < 4; i++) {
                uint32_t so = (uint32_t)((arow + i * 16) * 128 + ks * 32 + akb);
                so ^= (so >> 3) & 0x70;
                ldsm4(fa[i], base + so);
            }
            const uint32_t krow = (uint32_t)(ks * 16 + krl);
            #pragma unroll
            for (int j2 = 0; j2 < 4; j2++) {
                uint32_t cx = (uint32_t)((wn >> 3) + 2 * j2 + nsel);
                uint32_t so = krow * 512 + ((cx ^ (krow & 31)) * 16);
                uint32_t r[4];
                ldsm4t(r, base + ATILEB_ + so);
                fb[2 * j2 + 0][0] = r[0]; fb[2 * j2 + 0][1] = r[1];
                fb[2 * j2 + 1][0] = r[2]; fb[2 * j2 + 1][1] = r[3];
            }
            #pragma unroll
            for (int i = 0; i < 4; i++)
                #pragma unroll
                for (int j = 0; j < 8; j++)
                    mma16816(acc[i][j], fa[i], fb[j]);
        }
        __syncthreads();
        if (++buf == 3) buf = 0;
    }

    const int g  = lane >> 2, tg = lane & 3;
    const size_t row0 = ar0 + wm, col0 = bc0 + wn;
    #pragma unroll
    for (int i = 0; i < 4; i++) {
        #pragma unroll
        for (int j = 0; j < 8; j++) {
            size_t col = col0 + j * 8 + tg * 2;
            float bx = 0.0f, by = 0.0f;
            if (BIAS) { bx = bias[col]; by = bias[col + 1]; }
            #pragma unroll
            for (int half = 0; half < 2; half++) {
                size_t row = row0 + i * 16 + g + half * 8;
                float vx = acc[i][j][2 * half + 0] + bx;
                float vy = acc[i][j][2 * half + 1] + by;
                size_t gi = row * (size_t)N + col;
                if (RES) { vx += res[gi]; vy += res[gi + 1]; }
                if (RELU) { vx = fmaxf(vx, 0.0f); vy = fmaxf(vy, 0.0f); }
                if (OHALF) {
                    Oh[gi >> 1] = __halves2half2(__float2half_rn(vx),
                                                 __float2half_rn(vy));
                } else {
                    float2 o; o.x = vx; o.y = vy;
                    *(float2*)(C + gi) = o;
                }
            }
        }
    }
}

// ------------------------- tensor-core attention -----------------------------
// Block: 16 queries x 1 head.  Heavy-first scheduling: qt reversed.
#define QT_    16
#define NTL_   128
#define SROW_  1032
#define SBY_   (QT_ * SROW_ * 4)
#define P_OFF_ SBY_
#define Q_OFF_ (P_OFF_ + QT_ * 2048)
#define KV_OFF_ (Q_OFF_ + 2048)
#define KVB_   16384
#define RINV_OFF_ (KV_OFF_ + 2 * KVB_)
#define ATT_SM_ (RINV_OFF_ + 64)

__global__ __launch_bounds__(256, 1) void attn_tc_k(
    const __half* __restrict__ qkvh, __half* __restrict__ oh)
{
    extern __shared__ char smc[];
    const uint32_t sb = smem_u32(smc);
    float* S    = (float*)smc;
    float* Rinv = (float*)(smc + RINV_OFF_);

    const int tid = threadIdx.x, wid = tid >> 5, lane = tid & 31;
    const int qt = (int)gridDim.x - 1 - (int)blockIdx.x;   // heavy blocks first
    const int h = blockIdx.y, b = blockIdx.z;
    const int q0 = qt * QT_;
    const int nt = (q0 + QT_ + NTL_ - 1) / NTL_;

    const size_t hrow = (size_t)H_ * HS_;
    const __half* qg = qkvh + ((size_t)b * S_ + q0) * hrow + h * HS_;
    const __half* kg = qkvh + MD_     + (size_t)b * S_ * hrow + h * HS_;
    const __half* vg = qkvh + 2 * MD_ + (size_t)b * S_ * hrow + h * HS_;

    auto stageKV = [&](uint32_t dst, const __half* src, int t) {
        int j0 = t * NTL_;
        #pragma unroll
        for (int i = 0; i < 4; i++) {
            int id = tid + 256 * i;
            int r  = id >> 3;
            int cx = id & 7;
            uint32_t so = (uint32_t)(r * 128 + cx * 16);
            so ^= (so >> 3) & 0x70;
            CP16(dst + so, src + (size_t)(j0 + r) * hrow + cx * 8);
        }
    };

    if (tid < 128) {
        int r = tid >> 3, cx = tid & 7;
        uint32_t so = (uint32_t)(r * 128 + cx * 16);
        so ^= (so >> 3) & 0x70;
        CP16(sb + Q_OFF_ + so, qg + (size_t)r * hrow + cx * 8);
    }
    CPCOMMIT();
    stageKV(sb + KV_OFF_, kg, 0); CPCOMMIT();
    CPWAIT1();
    __syncthreads();

    uint32_t qf[4][4];
    {
        const int arow = lane & 15;
        const int akb  = (lane >> 4) * 16;
        #pragma unroll
        for (int ks = 0; ks < 4; ks++) {
            uint32_t so = (uint32_t)(arow * 128 + ks * 32 + akb);
            so ^= (so >> 3) & 0x70;
            ldsm4(qf[ks], sb + Q_OFF_ + so);
        }
    }

    for (int t = 0; t < nt; t++) {
        if (t + 1 < nt) { stageKV(sb + KV_OFF_ + ((t + 1) & 1) * KVB_, kg, t + 1); CPCOMMIT(); CPWAIT1(); }
        else            { CPWAIT0(); }
        __syncthreads();

        const uint32_t kb = sb + KV_OFF_ + (t & 1) * KVB_;
        #pragma unroll
        for (int sub = 0; sub < 2; sub++) {
            int n0 = (2 * wid + sub) * 8;
            float acc[4] = {0.0f, 0.0f, 0.0f, 0.0f};
            #pragma unroll
            for (int ks = 0; ks < 4; ks++) {
                uint32_t bf[2];
                uint32_t so = (uint32_t)((n0 + (lane & 7)) * 128 + ks * 32 + ((lane >> 3) & 1) * 16);
                so ^= (so >> 3) & 0x70;
                ldsm2(bf, kb + so);
                mma16816(acc, qf[ks], bf);
            }
            int g = lane >> 2, tg = lane & 3;
            int col = t * NTL_ + n0 + tg * 2;
            S[g * SROW_ + col]           = acc[0] * SCALE_;
            S[g * SROW_ + col + 1]       = acc[1] * SCALE_;
            S[(g + 8) * SROW_ + col]     = acc[2] * SCALE_;
            S[(g + 8) * SROW_ + col + 1] = acc[3] * SCALE_;
        }
        __syncthreads();
    }

    {
        const int jmax = nt * NTL_;
        __half* P = (__half*)(smc + P_OFF_);
        #pragma unroll
        for (int qq = 0; qq < 2; qq++) {
            int r  = 2 * wid + qq;
            int nq = q0 + r + 1;
            float m = -1e30f;
            for (int j = lane; j < nq; j += 32) m = fmaxf(m, S[r * SROW_ + j]);
            #pragma unroll
            for (int st = 16; st > 0; st >>= 1)
                m = fmaxf(m, __shfl_xor_sync(0xffffffff, m, st));
            float sum = 0.0f;
            for (int j = lane; j < jmax; j += 32) {
                float e = 0.0f;
                if (j < nq) { e = __expf(S[r * SROW_ + j] - m); sum += e; }
                int ch = j >> 3;
                uint32_t off = (uint32_t)(r * 2048 + ((ch ^ (r & 7)) * 16) + (j & 7) * 2);
                *(__half*)((char*)P + off) = __float2half_rn(e);
            }
            #pragma unroll
            for (int st = 16; st > 0; st >>= 1)
                sum += __shfl_xor_sync(0xffffffff, sum, st);
            if (lane == 0) Rinv[r] = 1.0f / sum;
        }
    }
    __syncthreads();

    float oacc[4] = {0.0f, 0.0f, 0.0f, 0.0f};
    stageKV(sb + KV_OFF_, vg, 0); CPCOMMIT();
    for (int t = 0; t < nt; t++) {
        if (t + 1 < nt) { stageKV(sb + KV_OFF_ + ((t + 1) & 1) * KVB_, vg, t + 1); CPCOMMIT(); CPWAIT1(); }
        else            { CPWAIT0(); }
        __syncthreads();

        const uint32_t vb = sb + KV_OFF_ + (t & 1) * KVB_;
        #pragma unroll
        for (int ks = 0; ks < 8; ks++) {
            uint32_t pf[4];
            {
                int r  = lane & 15;
                int ch = t * 16 + 2 * ks + (lane >> 4);
                uint32_t addr = (uint32_t)(P_OFF_ + r * 2048 + ((ch ^ (r & 7)) * 16));
                ldsm4(pf, sb + addr);
            }
            uint32_t vf[2];
            {
                int kr = ks * 16 + (lane & 15);
                int cx = wid;
                uint32_t so = (uint32_t)(kr * 128 + ((cx ^ (kr & 7)) * 16));
                ldsm2t(vf, vb + so);
            }
            mma16816(oacc, pf, vf);
        }
        __syncthreads();
    }

    {
        int g = lane >> 2, tg = lane & 3;
        int col = wid * 8 + tg * 2;
        #pragma unroll
        for (int half = 0; half < 2; half++) {
            int row = g + half * 8;
            float rv = Rinv[row];
            __half2 o = __halves2half2(__float2half_rn(oacc[2 * half + 0] * rv),
                                       __float2half_rn(oacc[2 * half + 1] * rv));
            *(__half2*)(oh + ((size_t)b * S_ + q0 + row) * hrow + h * HS_ + col) = o;
        }
    }
}

// ------------------------- driver -------------------------------------------
extern "C" void kernel_launch(void* const* d_in, const int* in_sizes, int n_in,
                              void* d_out, int out_size)
{
    const int*   idx   = (const int*)  d_in[0];
    const float* tok   = (const float*)d_in[1];
    const float* pos   = (const float*)d_in[2];
    const float* ln1g  = (const float*)d_in[3];
    const float* ln1b  = (const float*)d_in[4];
    const float* ln2g  = (const float*)d_in[5];
    const float* ln2b  = (const float*)d_in[6];
    const float* wq    = (const float*)d_in[7];
    const float* wk    = (const float*)d_in[8];
    const float* wv    = (const float*)d_in[9];
    const float* wo    = (const float*)d_in[10];
    const float* bo    = (const float*)d_in[11];
    const float* w1    = (const float*)d_in[12];
    const float* b1    = (const float*)d_in[13];
    const float* w2    = (const float*)d_in[14];
    const float* b2    = (const float*)d_in[15];
    const float* lnfg  = (const float*)d_in[16];
    const float* lnfb  = (const float*)d_in[17];
    const float* whead = (const float*)d_in[18];
    const float* bhead = (const float*)d_in[19];
    float* out = (float*)d_out;

    float *x, *xn;
    __half *qkvh, *ah, *hh, *wh;
    cudaGetSymbolAddress((void**)&x,    g_x);
    cudaGetSymbolAddress((void**)&xn,   g_xn);
    cudaGetSymbolAddress((void**)&qkvh, g_qkvh);
    cudaGetSymbolAddress((void**)&ah,   g_ah);
    cudaGetSymbolAddress((void**)&hh,   g_hh);
    cudaGetSymbolAddress((void**)&wh,   g_wh);

    cudaFuncSetAttribute(mma_gemm_k<false,false,false,true>,  cudaFuncAttributeMaxDynamicSharedMemorySize, SMTOT_);
    cudaFuncSetAttribute(mma_gemm_k<true,true,false,false>,   cudaFuncAttributeMaxDynamicSharedMemorySize, SMTOT_);
    cudaFuncSetAttribute(mma_gemm_k<true,false,true,true>,    cudaFuncAttributeMaxDynamicSharedMemorySize, SMTOT_);
    cudaFuncSetAttribute(mma_gemm_k<true,false,false,false>,  cudaFuncAttributeMaxDynamicSharedMemorySize, SMTOT_);
    cudaFuncSetAttribute(attn_tc_k, cudaFuncAttributeMaxDynamicSharedMemorySize, ATT_SM_);

    dim3 blk(256);

    // ---- weight fp16 conversion (MLP=2 per thread) ----
    {
        int nQ = (int)(4 * DD_ / 4);
        int nF = (int)(16 * DD_ / 4);
        int nH = (int)((size_t)D_ * V_ / 4);
        wsplit_k<<<(nQ/2 + 255)/256, blk>>>((const float4*)wq, (__half2*)(wh + WQ_OFF_), nQ);
        wsplit_k<<<(nQ/2 + 255)/256, blk>>>((const float4*)wk, (__half2*)(wh + WK_OFF_), nQ);
        wsplit_k<<<(nQ/2 + 255)/256, blk>>>((const float4*)wv, (__half2*)(wh + WV_OFF_), nQ);
        wsplit_k<<<(nQ/2 + 255)/256, blk>>>((const float4*)wo, (__half2*)(wh + WO_OFF_), nQ);
        wsplit_k<<<(nF/2 + 255)/256, blk>>>((const float4*)w1, (__half2*)(wh + W1_OFF_), nF);
        wsplit_k<<<(nF/2 + 255)/256, blk>>>((const float4*)w2, (__half2*)(wh + W2_OFF_), nF);
        wsplit_k<<<(nH/2 + 255)/256, blk>>>((const float4*)whead, (__half2*)(wh + WH_OFF_), nH);
    }

    embed_k<<<M_, blk>>>(idx, (const float4*)tok, (const float4*)pos, (float4*)x);

    for (int l = 0; l < L_; l++) {
        size_t oq = WQ_OFF_ + (size_t)l * DD_;
        size_t oo = WO_OFF_ + (size_t)l * DD_;
        size_t o1 = W1_OFF_ + (size_t)l * 4 * DD_;
        size_t o2 = W2_OFF_ + (size_t)l * 4 * DD_;

        layernorm_k<<<M_, blk>>>((const float4*)x, (const float4*)(ln1g + l * D_),
                                 (const float4*)(ln1b + l * D_), (float4*)xn,
                                 (__half2*)ah);

        // fused QKV -> fp16 qkv slabs
        mma_gemm_k<false,false,false,true><<<dim3(M_/128, D_/256, 3), blk, SMTOT_>>>(
            M_, D_, D_, ah, wh + oq, nullptr, nullptr, nullptr,
            (__half2*)qkvh, 4 * DD_, 0, MD_ / 2);

        attn_tc_k<<<dim3(S_ / QT_, H_, B_), 256, ATT_SM_>>>(qkvh, ah);

        // x = xn + att @ wo + bo
        mma_gemm_k<true,true,false,false><<<dim3(M_/128, D_/256), blk, SMTOT_>>>(
            M_, D_, D_, ah, wh + oo, bo + l * D_, xn, x,
            nullptr, 0, 0, 0);

        layernorm_k<<<M_, blk>>>((const float4*)x, (const float4*)(ln2g + l * D_),
                                 (const float4*)(ln2b + l * D_), (float4*)xn,
                                 (__half2*)ah);

        // h = relu(xn @ w1 + b1)  -> fp16 directly
        mma_gemm_k<true,false,true,true><<<dim3(M_/128, DFF_/256), blk, SMTOT_>>>(
            M_, DFF_, D_, ah, wh + o1,
            b1 + (size_t)l * DFF_, nullptr, nullptr,
            (__half2*)hh, 0, 0, 0);

        // x = xn + h @ w2 + b2
        mma_gemm_k<true,true,false,false><<<dim3(M_/128, D_/256), blk, SMTOT_>>>(
            M_, D_, DFF_, hh, wh + o2,
            b2 + l * D_, xn, x, nullptr, 0, 0, 0);
    }

    layernorm_k<<<M_, blk>>>((const float4*)x, (const float4*)lnfg,
                             (const float4*)lnfb, (float4*)xn,
                             (__half2*)ah);

    // logits = xn @ w_head + b_head
    mma_gemm_k<true,false,false,false><<<dim3(M_/128, V_/256), blk, SMTOT_>>>(
        M_, V_, D_, ah, wh + WH_OFF_,
        bhead, nullptr, out, nullptr, 0, 0, 0);
}

// round 12
// speedup vs baseline: 2.5119x; 1.0104x over previous
#include <cuda_runtime.h>
#include <cuda_fp16.h>
#include <cstdint>
#include <math.h>

// ---------------------------------------------------------------------------
// MinGPT forward.  B=4, S=1024, D=1024, H=16, HS=64, L=4, DFF=4096, V=32000.
// Round 12: 16B-store weight conversion, V-prefetch over softmax,
// 8B LN fp16 stores.  GEMM/attention numerics unchanged (R10/R11).
// ---------------------------------------------------------------------------

#define B_  4
#define S_  1024
#define D_  1024
#define H_  16
#define HS_ 64
#define L_  4
#define DFF_ 4096
#define V_  32000
#define M_  (B_ * S_)
#define MD_ ((size_t)M_ * D_)
#define EPS_ 1e-5f
#define SCALE_ 0.03125f        // D^-0.5 = 1/32 (reference uses d_model)

// ------------------------- scratch -----------------------------------------
__device__ float g_x  [M_ * D_];
__device__ float g_xn [M_ * D_];

__device__ __align__(16) __half g_qkvh[3 * M_ * D_];
__device__ __align__(16) __half g_ah[M_ * D_];
__device__ __align__(16) __half g_hh[M_ * DFF_];

#define DD_      ((size_t)D_ * D_)
#define WQ_OFF_  ((size_t)0)
#define WK_OFF_  (4 * DD_)
#define WV_OFF_  (8 * DD_)
#define WO_OFF_  (12 * DD_)
#define W1_OFF_  (16 * DD_)
#define W2_OFF_  (32 * DD_)
#define WH_OFF_  (48 * DD_)
#define WT_TOT_  (48 * DD_ + (size_t)D_ * V_)
__device__ __align__(16) __half g_wh[WT_TOT_];

// ------------------------- PTX helpers --------------------------------------
__device__ __forceinline__ uint32_t smem_u32(const void* p) {
    uint32_t a;
    asm("{ .reg .u64 t; cvta.to.shared.u64 t, %1; cvt.u32.u64 %0, t; }"
        : "=r"(a) : "l"(p));
    return a;
}
#define CP16(dst, src) \
    asm volatile("cp.async.cg.shared.global [%0], [%1], 16;" :: "r"(dst), "l"(src))
#define CPCOMMIT() asm volatile("cp.async.commit_group;" ::: "memory")
#define CPWAIT0()  asm volatile("cp.async.wait_group 0;" ::: "memory")
#define CPWAIT1()  asm volatile("cp.async.wait_group 1;" ::: "memory")
#define CPWAIT2()  asm volatile("cp.async.wait_group 2;" ::: "memory")

__device__ __forceinline__ void ldsm4(uint32_t* r, uint32_t addr) {
    asm volatile("ldmatrix.sync.aligned.m8n8.x4.shared.b16 {%0,%1,%2,%3}, [%4];"
        : "=r"(r[0]), "=r"(r[1]), "=r"(r[2]), "=r"(r[3]) : "r"(addr));
}
__device__ __forceinline__ void ldsm4t(uint32_t* r, uint32_t addr) {
    asm volatile("ldmatrix.sync.aligned.m8n8.x4.trans.shared.b16 {%0,%1,%2,%3}, [%4];"
        : "=r"(r[0]), "=r"(r[1]), "=r"(r[2]), "=r"(r[3]) : "r"(addr));
}
__device__ __forceinline__ void ldsm2(uint32_t* r, uint32_t addr) {
    asm volatile("ldmatrix.sync.aligned.m8n8.x2.shared.b16 {%0,%1}, [%2];"
        : "=r"(r[0]), "=r"(r[1]) : "r"(addr));
}
__device__ __forceinline__ void ldsm2t(uint32_t* r, uint32_t addr) {
    asm volatile("ldmatrix.sync.aligned.m8n8.x2.trans.shared.b16 {%0,%1}, [%2];"
        : "=r"(r[0]), "=r"(r[1]) : "r"(addr));
}
__device__ __forceinline__ void mma16816(float* d, const uint32_t* a, const uint32_t* b) {
    asm volatile(
        "mma.sync.aligned.m16n8k16.row.col.f32.f16.f16.f32 "
        "{%0,%1,%2,%3}, {%4,%5,%6,%7}, {%8,%9}, {%0,%1,%2,%3};"
        : "+f"(d[0]), "+f"(d[1]), "+f"(d[2]), "+f"(d[3])
        : "r"(a[0]), "r"(a[1]), "r"(a[2]), "r"(a[3]), "r"(b[0]), "r"(b[1]));
}

__device__ __forceinline__ uint32_t pack2h(float a, float b) {
    __half2 h = __halves2half2(__float2half_rn(a), __float2half_rn(b));
    return *(uint32_t*)&h;
}

// ------------------------- embedding ----------------------------------------
__global__ __launch_bounds__(256) void embed_k(
    const int* __restrict__ idx, const float4* __restrict__ tok,
    const float4* __restrict__ pos, float4* __restrict__ x)
{
    int row = blockIdx.x;
    int s   = row & (S_ - 1);
    int t   = idx[row];
    int c   = threadIdx.x;
    float4 tv = tok[(size_t)t * (D_ / 4) + c];
    float4 pv = pos[(size_t)s * (D_ / 4) + c];
    float4 o;
    o.x = tv.x + pv.x; o.y = tv.y + pv.y; o.z = tv.z + pv.z; o.w = tv.w + pv.w;
    x[(size_t)row * (D_ / 4) + c] = o;
}

// ------------------------- layer norm + fused fp16 convert -------------------
__global__ __launch_bounds__(256) void layernorm_k(
    const float4* __restrict__ x, const float4* __restrict__ g,
    const float4* __restrict__ bb, float4* __restrict__ y,
    uint2* __restrict__ oh)
{
    int row = blockIdx.x;
    int tid = threadIdx.x;
    __shared__ float red[256];

    float4 xv = x[(size_t)row * 256 + tid];
    float s = xv.x + xv.y + xv.z + xv.w;
    red[tid] = s; __syncthreads();
    #pragma unroll
    for (int st = 128; st > 0; st >>= 1) {
        if (tid < st) red[tid] += red[tid + st];
        __syncthreads();
    }
    float mu = red[0] * (1.0f / D_);
    __syncthreads();

    float dx = xv.x - mu, dy = xv.y - mu, dz = xv.z - mu, dw = xv.w - mu;
    float s2 = dx * dx + dy * dy + dz * dz + dw * dw;
    red[tid] = s2; __syncthreads();
    #pragma unroll
    for (int st = 128; st > 0; st >>= 1) {
        if (tid < st) red[tid] += red[tid + st];
        __syncthreads();
    }
    float inv = rsqrtf(red[0] * (1.0f / D_) + EPS_);

    float4 gv = g[tid], bv = bb[tid];
    float4 o;
    o.x = dx * inv * gv.x + bv.x;
    o.y = dy * inv * gv.y + bv.y;
    o.z = dz * inv * gv.z + bv.z;
    o.w = dw * inv * gv.w + bv.w;
    size_t i = (size_t)row * 256 + tid;
    y[i] = o;

    uint2 hp;
    hp.x = pack2h(o.x, o.y);
    hp.y = pack2h(o.z, o.w);
    oh[i] = hp;
}

// ------------------------- fp32 -> fp16 (weights), 16B stores ----------------
// thread handles float4 pairs (2i, 2i+1) and (2i+np, 2i+np+1) -> two float4
// stores of 8 packed halves each.  np = n4/2.
__global__ __launch_bounds__(256) void wsplit_k(
    const float4* __restrict__ x, uint4* __restrict__ h, int n4)
{
    int npair = n4 >> 1;                  // float4-pairs total
    int halfp = npair >> 1;
    int i = blockIdx.x * 256 + threadIdx.x;
    if (i >= halfp) return;
    #pragma unroll
    for (int m = 0; m < 2; m++) {
        int p = i + m * halfp;
        float4 v0 = x[2 * p];
        float4 v1 = x[2 * p + 1];
        uint4 o;
        o.x = pack2h(v0.x, v0.y);
        o.y = pack2h(v0.z, v0.w);
        o.z = pack2h(v1.x, v1.y);
        o.w = pack2h(v1.z, v1.w);
        h[p] = o;
    }
}

// ------------------------- mma.sync GEMM (3-stage pipeline) ------------------
#define ATILEB_ 16384
#define BTILEB_ 32768
#define BUFB_   (ATILEB_ + BTILEB_)        // 48 KB
#define SMTOT_  (3 * BUFB_)                // 144 KB

template<bool BIAS, bool RES, bool RELU, bool OHALF>
__global__ __launch_bounds__(256, 1) void mma_gemm_k(
    int M, int N, int K,
    const __half* __restrict__ Ah,
    const __half* __restrict__ Bw,
    const float* __restrict__ bias, const float* __restrict__ res,
    float* __restrict__ C,
    __half2* __restrict__ Oh,
    size_t bzS, size_t czS, size_t ozS)
{
    extern __shared__ char smem[];
    const uint32_t sb = smem_u32(smem);
    const int tid = threadIdx.x, wid = tid >> 5, lane = tid & 31;
    const int mb = blockIdx.x, nb = blockIdx.y;
    Bw += blockIdx.z * bzS;
    C  += blockIdx.z * czS;
    if (OHALF) Oh += blockIdx.z * ozS;
    const size_t ar0 = (size_t)mb * 128, bc0 = (size_t)nb * 256;
    const int wm = (wid >> 2) * 64, wn = (wid & 3) * 64;

    float acc[4][8][4];
    #pragma unroll
    for (int i = 0; i < 4; i++)
        #pragma unroll
        for (int j = 0; j < 8; j++)
            #pragma unroll
            for (int e = 0; e < 4; e++) acc[i][j][e] = 0.0f;

    const int nch = K >> 6;

    auto fill = [&](int buf, int c) {
        const size_t kof = (size_t)c << 6;
        const uint32_t bb = sb + buf * BUFB_;
        #pragma unroll
        for (int i = 0; i < 4; i++) {
            int id = tid + 256 * i;
            int r  = id >> 3;
            int cx = id & 7;
            uint32_t so = (uint32_t)(r * 128 + cx * 16);
            so ^= (so >> 3) & 0x70;
            size_t ai = (ar0 + r) * (size_t)K + kof + cx * 8;
            CP16(bb + so, Ah + ai);
        }
        #pragma unroll
        for (int i = 0; i < 8; i++) {
            int id = tid + 256 * i;
            int kr = id >> 5;
            int cx = id & 31;
            uint32_t so = (uint32_t)(kr * 512 + ((cx ^ (kr & 31)) * 16));
            size_t bi = (kof + kr) * (size_t)N + bc0 + cx * 8;
            CP16(bb + ATILEB_ + so, Bw + bi);
        }
    };

    fill(0, 0); CPCOMMIT();
    fill(1, 1); CPCOMMIT();

    uint32_t fa[4][4], fb[8][2];
    const int arow = wm + (lane & 15);
    const int akb  = (lane >> 4) * 16;
    const int krl  = lane & 15;
    const int nsel = lane >> 4;

    int buf = 0;
    for (int c = 0; c < nch; c++) {
        if (c + 2 < nch) {
            int nbuf = buf + 2; if (nbuf >= 3) nbuf -= 3;
            fill(nbuf, c + 2); CPCOMMIT(); CPWAIT2();
        } else if (c + 1 < nch) { CPWAIT1(); }
        else                    { CPWAIT0(); }
        __syncthreads();

        const uint32_t base = sb + buf * BUFB_;
        #pragma unroll
        for (int ks = 0; ks < 4; ks++) {
            #pragma unroll
            for (int i = 0; i < 4; i++) {
                uint32_t so = (uint32_t)((arow + i * 16) * 128 + ks * 32 + akb);
                so ^= (so >> 3) & 0x70;
                ldsm4(fa[i], base + so);
            }
            const uint32_t krow = (uint32_t)(ks * 16 + krl);
            #pragma unroll
            for (int j2 = 0; j2 < 4; j2++) {
                uint32_t cx = (uint32_t)((wn >> 3) + 2 * j2 + nsel);
                uint32_t so = krow * 512 + ((cx ^ (krow & 31)) * 16);
                uint32_t r[4];
                ldsm4t(r, base + ATILEB_ + so);
                fb[2 * j2 + 0][0] = r[0]; fb[2 * j2 + 0][1] = r[1];
                fb[2 * j2 + 1][0] = r[2]; fb[2 * j2 + 1][1] = r[3];
            }
            #pragma unroll
            for (int i = 0; i < 4; i++)
                #pragma unroll
                for (int j = 0; j < 8; j++)
                    mma16816(acc[i][j], fa[i], fb[j]);
        }
        __syncthreads();
        if (++buf == 3) buf = 0;
    }

    const int g  = lane >> 2, tg = lane & 3;
    const size_t row0 = ar0 + wm, col0 = bc0 + wn;
    #pragma unroll
    for (int i = 0; i < 4; i++) {
        #pragma unroll
        for (int j = 0; j < 8; j++) {
            size_t col = col0 + j * 8 + tg * 2;
            float bx = 0.0f, by = 0.0f;
            if (BIAS) { bx = bias[col]; by = bias[col + 1]; }
            #pragma unroll
            for (int half = 0; half < 2; half++) {
                size_t row = row0 + i * 16 + g + half * 8;
                float vx = acc[i][j][2 * half + 0] + bx;
                float vy = acc[i][j][2 * half + 1] + by;
                size_t gi = row * (size_t)N + col;
                if (RES) { vx += res[gi]; vy += res[gi + 1]; }
                if (RELU) { vx = fmaxf(vx, 0.0f); vy = fmaxf(vy, 0.0f); }
                if (OHALF) {
                    Oh[gi >> 1] = __halves2half2(__float2half_rn(vx),
                                                 __float2half_rn(vy));
                } else {
                    float2 o; o.x = vx; o.y = vy;
                    *(float2*)(C + gi) = o;
                }
            }
        }
    }
}

// ------------------------- tensor-core attention -----------------------------
#define QT_    16
#define NTL_   128
#define SROW_  1032
#define SBY_   (QT_ * SROW_ * 4)
#define P_OFF_ SBY_
#define Q_OFF_ (P_OFF_ + QT_ * 2048)
#define KV_OFF_ (Q_OFF_ + 2048)
#define KVB_   16384
#define RINV_OFF_ (KV_OFF_ + 2 * KVB_)
#define ATT_SM_ (RINV_OFF_ + 64)

__global__ __launch_bounds__(256, 1) void attn_tc_k(
    const __half* __restrict__ qkvh, __half* __restrict__ oh)
{
    extern __shared__ char smc[];
    const uint32_t sb = smem_u32(smc);
    float* S    = (float*)smc;
    float* Rinv = (float*)(smc + RINV_OFF_);

    const int tid = threadIdx.x, wid = tid >> 5, lane = tid & 31;
    const int qt = (int)gridDim.x - 1 - (int)blockIdx.x;
    const int h = blockIdx.y, b = blockIdx.z;
    const int q0 = qt * QT_;
    const int nt = (q0 + QT_ + NTL_ - 1) / NTL_;

    const size_t hrow = (size_t)H_ * HS_;
    const __half* qg = qkvh + ((size_t)b * S_ + q0) * hrow + h * HS_;
    const __half* kg = qkvh + MD_     + (size_t)b * S_ * hrow + h * HS_;
    const __half* vg = qkvh + 2 * MD_ + (size_t)b * S_ * hrow + h * HS_;

    auto stageKV = [&](uint32_t dst, const __half* src, int t) {
        int j0 = t * NTL_;
        #pragma unroll
        for (int i = 0; i < 4; i++) {
            int id = tid + 256 * i;
            int r  = id >> 3;
            int cx = id & 7;
            uint32_t so = (uint32_t)(r * 128 + cx * 16);
            so ^= (so >> 3) & 0x70;
            CP16(dst + so, src + (size_t)(j0 + r) * hrow + cx * 8);
        }
    };

    if (tid < 128) {
        int r = tid >> 3, cx = tid & 7;
        uint32_t so = (uint32_t)(r * 128 + cx * 16);
        so ^= (so >> 3) & 0x70;
        CP16(sb + Q_OFF_ + so, qg + (size_t)r * hrow + cx * 8);
    }
    CPCOMMIT();
    stageKV(sb + KV_OFF_, kg, 0); CPCOMMIT();
    CPWAIT1();
    __syncthreads();

    uint32_t qf[4][4];
    {
        const int arow = lane & 15;
        const int akb  = (lane >> 4) * 16;
        #pragma unroll
        for (int ks = 0; ks < 4; ks++) {
            uint32_t so = (uint32_t)(arow * 128 + ks * 32 + akb);
            so ^= (so >> 3) & 0x70;
            ldsm4(qf[ks], sb + Q_OFF_ + so);
        }
    }

    // ---- pass A: scores ----
    for (int t = 0; t < nt; t++) {
        if (t + 1 < nt) { stageKV(sb + KV_OFF_ + ((t + 1) & 1) * KVB_, kg, t + 1); CPCOMMIT(); CPWAIT1(); }
        else            { CPWAIT0(); }
        __syncthreads();

        const uint32_t kb = sb + KV_OFF_ + (t & 1) * KVB_;
        #pragma unroll
        for (int sub = 0; sub < 2; sub++) {
            int n0 = (2 * wid + sub) * 8;
            float acc[4] = {0.0f, 0.0f, 0.0f, 0.0f};
            #pragma unroll
            for (int ks = 0; ks < 4; ks++) {
                uint32_t bf[2];
                uint32_t so = (uint32_t)((n0 + (lane & 7)) * 128 + ks * 32 + ((lane >> 3) & 1) * 16);
                so ^= (so >> 3) & 0x70;
                ldsm2(bf, kb + so);
                mma16816(acc, qf[ks], bf);
            }
            int g = lane >> 2, tg = lane & 3;
            int col = t * NTL_ + n0 + tg * 2;
            S[g * SROW_ + col]           = acc[0] * SCALE_;
            S[g * SROW_ + col + 1]       = acc[1] * SCALE_;
            S[(g + 8) * SROW_ + col]     = acc[2] * SCALE_;
            S[(g + 8) * SROW_ + col + 1] = acc[3] * SCALE_;
        }
        __syncthreads();
    }

    // V tile 0 prefetch overlaps the softmax below
    stageKV(sb + KV_OFF_, vg, 0); CPCOMMIT();

    // ---- softmax (fp32) -> P fp16, swizzled ----
    {
        const int jmax = nt * NTL_;
        __half* P = (__half*)(smc + P_OFF_);
        #pragma unroll
        for (int qq = 0; qq < 2; qq++) {
            int r  = 2 * wid + qq;
            int nq = q0 + r + 1;
            float m = -1e30f;
            for (int j = lane; j < nq; j += 32) m = fmaxf(m, S[r * SROW_ + j]);
            #pragma unroll
            for (int st = 16; st > 0; st >>= 1)
                m = fmaxf(m, __shfl_xor_sync(0xffffffff, m, st));
            float sum = 0.0f;
            for (int j = lane; j < jmax; j += 32) {
                float e = 0.0f;
                if (j < nq) { e = __expf(S[r * SROW_ + j] - m); sum += e; }
                int ch = j >> 3;
                uint32_t off = (uint32_t)(r * 2048 + ((ch ^ (r & 7)) * 16) + (j & 7) * 2);
                *(__half*)((char*)P + off) = __float2half_rn(e);
            }
            #pragma unroll
            for (int st = 16; st > 0; st >>= 1)
                sum += __shfl_xor_sync(0xffffffff, sum, st);
            if (lane == 0) Rinv[r] = 1.0f / sum;
        }
    }
    __syncthreads();

    // ---- pass B: O = P @ V ----
    float oacc[4] = {0.0f, 0.0f, 0.0f, 0.0f};
    for (int t = 0; t < nt; t++) {
        if (t + 1 < nt) { stageKV(sb + KV_OFF_ + ((t + 1) & 1) * KVB_, vg, t + 1); CPCOMMIT(); CPWAIT1(); }
        else            { CPWAIT0(); }
        __syncthreads();

        const uint32_t vb = sb + KV_OFF_ + (t & 1) * KVB_;
        #pragma unroll
        for (int ks = 0; ks < 8; ks++) {
            uint32_t pf[4];
            {
                int r  = lane & 15;
                int ch = t * 16 + 2 * ks + (lane >> 4);
                uint32_t addr = (uint32_t)(P_OFF_ + r * 2048 + ((ch ^ (r & 7)) * 16));
                ldsm4(pf, sb + addr);
            }
            uint32_t vf[2];
            {
                int kr = ks * 16 + (lane & 15);
                int cx = wid;
                uint32_t so = (uint32_t)(kr * 128 + ((cx ^ (kr & 7)) * 16));
                ldsm2t(vf, vb + so);
            }
            mma16816(oacc, pf, vf);
        }
        __syncthreads();
    }

    {
        int g = lane >> 2, tg = lane & 3;
        int col = wid * 8 + tg * 2;
        #pragma unroll
        for (int half = 0; half < 2; half++) {
            int row = g + half * 8;
            float rv = Rinv[row];
            __half2 o = __halves2half2(__float2half_rn(oacc[2 * half + 0] * rv),
                                       __float2half_rn(oacc[2 * half + 1] * rv));
            *(__half2*)(oh + ((size_t)b * S_ + q0 + row) * hrow + h * HS_ + col) = o;
        }
    }
}

// ------------------------- driver -------------------------------------------
extern "C" void kernel_launch(void* const* d_in, const int* in_sizes, int n_in,
                              void* d_out, int out_size)
{
    const int*   idx   = (const int*)  d_in[0];
    const float* tok   = (const float*)d_in[1];
    const float* pos   = (const float*)d_in[2];
    const float* ln1g  = (const float*)d_in[3];
    const float* ln1b  = (const float*)d_in[4];
    const float* ln2g  = (const float*)d_in[5];
    const float* ln2b  = (const float*)d_in[6];
    const float* wq    = (const float*)d_in[7];
    const float* wk    = (const float*)d_in[8];
    const float* wv    = (const float*)d_in[9];
    const float* wo    = (const float*)d_in[10];
    const float* bo    = (const float*)d_in[11];
    const float* w1    = (const float*)d_in[12];
    const float* b1    = (const float*)d_in[13];
    const float* w2    = (const float*)d_in[14];
    const float* b2    = (const float*)d_in[15];
    const float* lnfg  = (const float*)d_in[16];
    const float* lnfb  = (const float*)d_in[17];
    const float* whead = (const float*)d_in[18];
    const float* bhead = (const float*)d_in[19];
    float* out = (float*)d_out;

    float *x, *xn;
    __half *qkvh, *ah, *hh, *wh;
    cudaGetSymbolAddress((void**)&x,    g_x);
    cudaGetSymbolAddress((void**)&xn,   g_xn);
    cudaGetSymbolAddress((void**)&qkvh, g_qkvh);
    cudaGetSymbolAddress((void**)&ah,   g_ah);
    cudaGetSymbolAddress((void**)&hh,   g_hh);
    cudaGetSymbolAddress((void**)&wh,   g_wh);

    cudaFuncSetAttribute(mma_gemm_k<false,false,false,true>,  cudaFuncAttributeMaxDynamicSharedMemorySize, SMTOT_);
    cudaFuncSetAttribute(mma_gemm_k<true,true,false,false>,   cudaFuncAttributeMaxDynamicSharedMemorySize, SMTOT_);
    cudaFuncSetAttribute(mma_gemm_k<true,false,true,true>,    cudaFuncAttributeMaxDynamicSharedMemorySize, SMTOT_);
    cudaFuncSetAttribute(mma_gemm_k<true,false,false,false>,  cudaFuncAttributeMaxDynamicSharedMemorySize, SMTOT_);
    cudaFuncSetAttribute(attn_tc_k, cudaFuncAttributeMaxDynamicSharedMemorySize, ATT_SM_);

    dim3 blk(256);

    // ---- weight fp16 conversion (16B stores, MLP=2) ----
    {
        int nQ = (int)(4 * DD_ / 4);
        int nF = (int)(16 * DD_ / 4);
        int nH = (int)((size_t)D_ * V_ / 4);
        wsplit_k<<<(nQ/4 + 255)/256, blk>>>((const float4*)wq, (uint4*)(wh + WQ_OFF_), nQ);
        wsplit_k<<<(nQ/4 + 255)/256, blk>>>((const float4*)wk, (uint4*)(wh + WK_OFF_), nQ);
        wsplit_k<<<(nQ/4 + 255)/256, blk>>>((const float4*)wv, (uint4*)(wh + WV_OFF_), nQ);
        wsplit_k<<<(nQ/4 + 255)/256, blk>>>((const float4*)wo, (uint4*)(wh + WO_OFF_), nQ);
        wsplit_k<<<(nF/4 + 255)/256, blk>>>((const float4*)w1, (uint4*)(wh + W1_OFF_), nF);
        wsplit_k<<<(nF/4 + 255)/256, blk>>>((const float4*)w2, (uint4*)(wh + W2_OFF_), nF);
        wsplit_k<<<(nH/4 + 255)/256, blk>>>((const float4*)whead, (uint4*)(wh + WH_OFF_), nH);
    }

    embed_k<<<M_, blk>>>(idx, (const float4*)tok, (const float4*)pos, (float4*)x);

    for (int l = 0; l < L_; l++) {
        size_t oq = WQ_OFF_ + (size_t)l * DD_;
        size_t oo = WO_OFF_ + (size_t)l * DD_;
        size_t o1 = W1_OFF_ + (size_t)l * 4 * DD_;
        size_t o2 = W2_OFF_ + (size_t)l * 4 * DD_;

        layernorm_k<<<M_, blk>>>((const float4*)x, (const float4*)(ln1g + l * D_),
                                 (const float4*)(ln1b + l * D_), (float4*)xn,
                                 (uint2*)ah);

        // fused QKV -> fp16 qkv slabs
        mma_gemm_k<false,false,false,true><<<dim3(M_/128, D_/256, 3), blk, SMTOT_>>>(
            M_, D_, D_, ah, wh + oq, nullptr, nullptr, nullptr,
            (__half2*)qkvh, 4 * DD_, 0, MD_ / 2);

        attn_tc_k<<<dim3(S_ / QT_, H_, B_), 256, ATT_SM_>>>(qkvh, ah);

        // x = xn + att @ wo + bo
        mma_gemm_k<true,true,false,false><<<dim3(M_/128, D_/256), blk, SMTOT_>>>(
            M_, D_, D_, ah, wh + oo, bo + l * D_, xn, x,
            nullptr, 0, 0, 0);

        layernorm_k<<<M_, blk>>>((const float4*)x, (const float4*)(ln2g + l * D_),
                                 (const float4*)(ln2b + l * D_), (float4*)xn,
                                 (uint2*)ah);

        // h = relu(xn @ w1 + b1)  -> fp16 directly
        mma_gemm_k<true,false,true,true><<<dim3(M_/128, DFF_/256), blk, SMTOT_>>>(
            M_, DFF_, D_, ah, wh + o1,
            b1 + (size_t)l * DFF_, nullptr, nullptr,
            (__half2*)hh, 0, 0, 0);

        // x = xn + h @ w2 + b2
        mma_gemm_k<true,true,false,false><<<dim3(M_/128, D_/256), blk, SMTOT_>>>(
            M_, D_, DFF_, hh, wh + o2,
            b2 + l * D_, xn, x, nullptr, 0, 0, 0);
    }

    layernorm_k<<<M_, blk>>>((const float4*)x, (const float4*)lnfg,
                             (const float4*)lnfb, (float4*)xn,
                             (uint2*)ah);

    // logits = xn @ w_head + b_head
    mma_gemm_k<true,false,false,false><<<dim3(M_/128, V_/256), blk, SMTOT_>>>(
        M_, V_, D_, ah, wh + WH_OFF_,
        bhead, nullptr, out, nullptr, 0, 0, 0);
}

// round 13
// speedup vs baseline: 2.5349x; 1.0092x over previous
#include <cuda_runtime.h>
#include <cuda_fp16.h>
#include <cstdint>
#include <math.h>

// ---------------------------------------------------------------------------
// MinGPT forward.  B=4, S=1024, D=1024, H=16, HS=64, L=4, DFF=4096, V=32000.
// Round 13: weight conversion forked onto a side stream (overlapped with
// layer-0 compute, rejoined before layer 1).  Numerics identical to R12.
// ---------------------------------------------------------------------------

#define B_  4
#define S_  1024
#define D_  1024
#define H_  16
#define HS_ 64
#define L_  4
#define DFF_ 4096
#define V_  32000
#define M_  (B_ * S_)
#define MD_ ((size_t)M_ * D_)
#define EPS_ 1e-5f
#define SCALE_ 0.03125f        // D^-0.5 = 1/32 (reference uses d_model)

// ------------------------- scratch -----------------------------------------
__device__ float g_x  [M_ * D_];
__device__ float g_xn [M_ * D_];

__device__ __align__(16) __half g_qkvh[3 * M_ * D_];
__device__ __align__(16) __half g_ah[M_ * D_];
__device__ __align__(16) __half g_hh[M_ * DFF_];

#define DD_      ((size_t)D_ * D_)
#define WQ_OFF_  ((size_t)0)
#define WK_OFF_  (4 * DD_)
#define WV_OFF_  (8 * DD_)
#define WO_OFF_  (12 * DD_)
#define W1_OFF_  (16 * DD_)
#define W2_OFF_  (32 * DD_)
#define WH_OFF_  (48 * DD_)
#define WT_TOT_  (48 * DD_ + (size_t)D_ * V_)
__device__ __align__(16) __half g_wh[WT_TOT_];

// ------------------------- PTX helpers --------------------------------------
__device__ __forceinline__ uint32_t smem_u32(const void* p) {
    uint32_t a;
    asm("{ .reg .u64 t; cvta.to.shared.u64 t, %1; cvt.u32.u64 %0, t; }"
        : "=r"(a) : "l"(p));
    return a;
}
#define CP16(dst, src) \
    asm volatile("cp.async.cg.shared.global [%0], [%1], 16;" :: "r"(dst), "l"(src))
#define CPCOMMIT() asm volatile("cp.async.commit_group;" ::: "memory")
#define CPWAIT0()  asm volatile("cp.async.wait_group 0;" ::: "memory")
#define CPWAIT1()  asm volatile("cp.async.wait_group 1;" ::: "memory")
#define CPWAIT2()  asm volatile("cp.async.wait_group 2;" ::: "memory")

__device__ __forceinline__ void ldsm4(uint32_t* r, uint32_t addr) {
    asm volatile("ldmatrix.sync.aligned.m8n8.x4.shared.b16 {%0,%1,%2,%3}, [%4];"
        : "=r"(r[0]), "=r"(r[1]), "=r"(r[2]), "=r"(r[3]) : "r"(addr));
}
__device__ __forceinline__ void ldsm4t(uint32_t* r, uint32_t addr) {
    asm volatile("ldmatrix.sync.aligned.m8n8.x4.trans.shared.b16 {%0,%1,%2,%3}, [%4];"
        : "=r"(r[0]), "=r"(r[1]), "=r"(r[2]), "=r"(r[3]) : "r"(addr));
}
__device__ __forceinline__ void ldsm2(uint32_t* r, uint32_t addr) {
    asm volatile("ldmatrix.sync.aligned.m8n8.x2.shared.b16 {%0,%1}, [%2];"
        : "=r"(r[0]), "=r"(r[1]) : "r"(addr));
}
__device__ __forceinline__ void ldsm2t(uint32_t* r, uint32_t addr) {
    asm volatile("ldmatrix.sync.aligned.m8n8.x2.trans.shared.b16 {%0,%1}, [%2];"
        : "=r"(r[0]), "=r"(r[1]) : "r"(addr));
}
__device__ __forceinline__ void mma16816(float* d, const uint32_t* a, const uint32_t* b) {
    asm volatile(
        "mma.sync.aligned.m16n8k16.row.col.f32.f16.f16.f32 "
        "{%0,%1,%2,%3}, {%4,%5,%6,%7}, {%8,%9}, {%0,%1,%2,%3};"
        : "+f"(d[0]), "+f"(d[1]), "+f"(d[2]), "+f"(d[3])
        : "r"(a[0]), "r"(a[1]), "r"(a[2]), "r"(a[3]), "r"(b[0]), "r"(b[1]));
}

__device__ __forceinline__ uint32_t pack2h(float a, float b) {
    __half2 h = __halves2half2(__float2half_rn(a), __float2half_rn(b));
    return *(uint32_t*)&h;
}

// ------------------------- embedding ----------------------------------------
__global__ __launch_bounds__(256) void embed_k(
    const int* __restrict__ idx, const float4* __restrict__ tok,
    const float4* __restrict__ pos, float4* __restrict__ x)
{
    int row = blockIdx.x;
    int s   = row & (S_ - 1);
    int t   = idx[row];
    int c   = threadIdx.x;
    float4 tv = tok[(size_t)t * (D_ / 4) + c];
    float4 pv = pos[(size_t)s * (D_ / 4) + c];
    float4 o;
    o.x = tv.x + pv.x; o.y = tv.y + pv.y; o.z = tv.z + pv.z; o.w = tv.w + pv.w;
    x[(size_t)row * (D_ / 4) + c] = o;
}

// ------------------------- layer norm + fused fp16 convert -------------------
__global__ __launch_bounds__(256) void layernorm_k(
    const float4* __restrict__ x, const float4* __restrict__ g,
    const float4* __restrict__ bb, float4* __restrict__ y,
    uint2* __restrict__ oh)
{
    int row = blockIdx.x;
    int tid = threadIdx.x;
    __shared__ float red[256];

    float4 xv = x[(size_t)row * 256 + tid];
    float s = xv.x + xv.y + xv.z + xv.w;
    red[tid] = s; __syncthreads();
    #pragma unroll
    for (int st = 128; st > 0; st >>= 1) {
        if (tid < st) red[tid] += red[tid + st];
        __syncthreads();
    }
    float mu = red[0] * (1.0f / D_);
    __syncthreads();

    float dx = xv.x - mu, dy = xv.y - mu, dz = xv.z - mu, dw = xv.w - mu;
    float s2 = dx * dx + dy * dy + dz * dz + dw * dw;
    red[tid] = s2; __syncthreads();
    #pragma unroll
    for (int st = 128; st > 0; st >>= 1) {
        if (tid < st) red[tid] += red[tid + st];
        __syncthreads();
    }
    float inv = rsqrtf(red[0] * (1.0f / D_) + EPS_);

    float4 gv = g[tid], bv = bb[tid];
    float4 o;
    o.x = dx * inv * gv.x + bv.x;
    o.y = dy * inv * gv.y + bv.y;
    o.z = dz * inv * gv.z + bv.z;
    o.w = dw * inv * gv.w + bv.w;
    size_t i = (size_t)row * 256 + tid;
    y[i] = o;

    uint2 hp;
    hp.x = pack2h(o.x, o.y);
    hp.y = pack2h(o.z, o.w);
    oh[i] = hp;
}

// ------------------------- fp32 -> fp16 (weights), 16B stores, MLP=4 --------
__global__ __launch_bounds__(256) void wsplit_k(
    const float4* __restrict__ x, uint4* __restrict__ h, int n4)
{
    int npair = n4 >> 1;                  // 16B output units
    int quarter = npair >> 2;
    int i = blockIdx.x * 256 + threadIdx.x;
    if (i >= quarter) return;
    #pragma unroll
    for (int m = 0; m < 4; m++) {
        int p = i + m * quarter;
        float4 v0 = x[2 * p];
        float4 v1 = x[2 * p + 1];
        uint4 o;
        o.x = pack2h(v0.x, v0.y);
        o.y = pack2h(v0.z, v0.w);
        o.z = pack2h(v1.x, v1.y);
        o.w = pack2h(v1.z, v1.w);
        h[p] = o;
    }
}

// ------------------------- mma.sync GEMM (3-stage pipeline) ------------------
#define ATILEB_ 16384
#define BTILEB_ 32768
#define BUFB_   (ATILEB_ + BTILEB_)        // 48 KB
#define SMTOT_  (3 * BUFB_)                // 144 KB

template<bool BIAS, bool RES, bool RELU, bool OHALF>
__global__ __launch_bounds__(256, 1) void mma_gemm_k(
    int M, int N, int K,
    const __half* __restrict__ Ah,
    const __half* __restrict__ Bw,
    const float* __restrict__ bias, const float* __restrict__ res,
    float* __restrict__ C,
    __half2* __restrict__ Oh,
    size_t bzS, size_t czS, size_t ozS)
{
    extern __shared__ char smem[];
    const uint32_t sb = smem_u32(smem);
    const int tid = threadIdx.x, wid = tid >> 5, lane = tid & 31;
    const int mb = blockIdx.x, nb = blockIdx.y;
    Bw += blockIdx.z * bzS;
    C  += blockIdx.z * czS;
    if (OHALF) Oh += blockIdx.z * ozS;
    const size_t ar0 = (size_t)mb * 128, bc0 = (size_t)nb * 256;
    const int wm = (wid >> 2) * 64, wn = (wid & 3) * 64;

    float acc[4][8][4];
    #pragma unroll
    for (int i = 0; i < 4; i++)
        #pragma unroll
        for (int j = 0; j < 8; j++)
            #pragma unroll
            for (int e = 0; e < 4; e++) acc[i][j][e] = 0.0f;

    const int nch = K >> 6;

    auto fill = [&](int buf, int c) {
        const size_t kof = (size_t)c << 6;
        const uint32_t bb = sb + buf * BUFB_;
        #pragma unroll
        for (int i = 0; i < 4; i++) {
            int id = tid + 256 * i;
            int r  = id >> 3;
            int cx = id & 7;
            uint32_t so = (uint32_t)(r * 128 + cx * 16);
            so ^= (so >> 3) & 0x70;
            size_t ai = (ar0 + r) * (size_t)K + kof + cx * 8;
            CP16(bb + so, Ah + ai);
        }
        #pragma unroll
        for (int i = 0; i < 8; i++) {
            int id = tid + 256 * i;
            int kr = id >> 5;
            int cx = id & 31;
            uint32_t so = (uint32_t)(kr * 512 + ((cx ^ (kr & 31)) * 16));
            size_t bi = (kof + kr) * (size_t)N + bc0 + cx * 8;
            CP16(bb + ATILEB_ + so, Bw + bi);
        }
    };

    fill(0, 0); CPCOMMIT();
    fill(1, 1); CPCOMMIT();

    uint32_t fa[4][4], fb[8][2];
    const int arow = wm + (lane & 15);
    const int akb  = (lane >> 4) * 16;
    const int krl  = lane & 15;
    const int nsel = lane >> 4;

    int buf = 0;
    for (int c = 0; c < nch; c++) {
        if (c + 2 < nch) {
            int nbuf = buf + 2; if (nbuf >= 3) nbuf -= 3;
            fill(nbuf, c + 2); CPCOMMIT(); CPWAIT2();
        } else if (c + 1 < nch) { CPWAIT1(); }
        else                    { CPWAIT0(); }
        __syncthreads();

        const uint32_t base = sb + buf * BUFB_;
        #pragma unroll
        for (int ks = 0; ks < 4; ks++) {
            #pragma unroll
            for (int i = 0; i < 4; i++) {
                uint32_t so = (uint32_t)((arow + i * 16) * 128 + ks * 32 + akb);
                so ^= (so >> 3) & 0x70;
                ldsm4(fa[i], base + so);
            }
            const uint32_t krow = (uint32_t)(ks * 16 + krl);
            #pragma unroll
            for (int j2 = 0; j2 < 4; j2++) {
                uint32_t cx = (uint32_t)((wn >> 3) + 2 * j2 + nsel);
                uint32_t so = krow * 512 + ((cx ^ (krow & 31)) * 16);
                uint32_t r[4];
                ldsm4t(r, base + ATILEB_ + so);
                fb[2 * j2 + 0][0] = r[0]; fb[2 * j2 + 0][1] = r[1];
                fb[2 * j2 + 1][0] = r[2]; fb[2 * j2 + 1][1] = r[3];
            }
            #pragma unroll
            for (int i = 0; i < 4; i++)
                #pragma unroll
                for (int j = 0; j < 8; j++)
                    mma16816(acc[i][j], fa[i], fb[j]);
        }
        __syncthreads();
        if (++buf == 3) buf = 0;
    }

    const int g  = lane >> 2, tg = lane & 3;
    const size_t row0 = ar0 + wm, col0 = bc0 + wn;
    #pragma unroll
    for (int i = 0; i < 4; i++) {
        #pragma unroll
        for (int j = 0; j < 8; j++) {
            size_t col = col0 + j * 8 + tg * 2;
            float bx = 0.0f, by = 0.0f;
            if (BIAS) { bx = bias[col]; by = bias[col + 1]; }
            #pragma unroll
            for (int half = 0; half < 2; half++) {
                size_t row = row0 + i * 16 + g + half * 8;
                float vx = acc[i][j][2 * half + 0] + bx;
                float vy = acc[i][j][2 * half + 1] + by;
                size_t gi = row * (size_t)N + col;
                if (RES) { vx += res[gi]; vy += res[gi + 1]; }
                if (RELU) { vx = fmaxf(vx, 0.0f); vy = fmaxf(vy, 0.0f); }
                if (OHALF) {
                    Oh[gi >> 1] = __halves2half2(__float2half_rn(vx),
                                                 __float2half_rn(vy));
                } else {
                    float2 o; o.x = vx; o.y = vy;
                    *(float2*)(C + gi) = o;
                }
            }
        }
    }
}

// ------------------------- tensor-core attention -----------------------------
#define QT_    16
#define NTL_   128
#define SROW_  1032
#define SBY_   (QT_ * SROW_ * 4)
#define P_OFF_ SBY_
#define Q_OFF_ (P_OFF_ + QT_ * 2048)
#define KV_OFF_ (Q_OFF_ + 2048)
#define KVB_   16384
#define RINV_OFF_ (KV_OFF_ + 2 * KVB_)
#define ATT_SM_ (RINV_OFF_ + 64)

__global__ __launch_bounds__(256, 1) void attn_tc_k(
    const __half* __restrict__ qkvh, __half* __restrict__ oh)
{
    extern __shared__ char smc[];
    const uint32_t sb = smem_u32(smc);
    float* S    = (float*)smc;
    float* Rinv = (float*)(smc + RINV_OFF_);

    const int tid = threadIdx.x, wid = tid >> 5, lane = tid & 31;
    const int qt = (int)gridDim.x - 1 - (int)blockIdx.x;
    const int h = blockIdx.y, b = blockIdx.z;
    const int q0 = qt * QT_;
    const int nt = (q0 + QT_ + NTL_ - 1) / NTL_;

    const size_t hrow = (size_t)H_ * HS_;
    const __half* qg = qkvh + ((size_t)b * S_ + q0) * hrow + h * HS_;
    const __half* kg = qkvh + MD_     + (size_t)b * S_ * hrow + h * HS_;
    const __half* vg = qkvh + 2 * MD_ + (size_t)b * S_ * hrow + h * HS_;

    auto stageKV = [&](uint32_t dst, const __half* src, int t) {
        int j0 = t * NTL_;
        #pragma unroll
        for (int i = 0; i < 4; i++) {
            int id = tid + 256 * i;
            int r  = id >> 3;
            int cx = id & 7;
            uint32_t so = (uint32_t)(r * 128 + cx * 16);
            so ^= (so >> 3) & 0x70;
            CP16(dst + so, src + (size_t)(j0 + r) * hrow + cx * 8);
        }
    };

    if (tid < 128) {
        int r = tid >> 3, cx = tid & 7;
        uint32_t so = (uint32_t)(r * 128 + cx * 16);
        so ^= (so >> 3) & 0x70;
        CP16(sb + Q_OFF_ + so, qg + (size_t)r * hrow + cx * 8);
    }
    CPCOMMIT();
    stageKV(sb + KV_OFF_, kg, 0); CPCOMMIT();
    CPWAIT1();
    __syncthreads();

    uint32_t qf[4][4];
    {
        const int arow = lane & 15;
        const int akb  = (lane >> 4) * 16;
        #pragma unroll
        for (int ks = 0; ks < 4; ks++) {
            uint32_t so = (uint32_t)(arow * 128 + ks * 32 + akb);
            so ^= (so >> 3) & 0x70;
            ldsm4(qf[ks], sb + Q_OFF_ + so);
        }
    }

    for (int t = 0; t < nt; t++) {
        if (t + 1 < nt) { stageKV(sb + KV_OFF_ + ((t + 1) & 1) * KVB_, kg, t + 1); CPCOMMIT(); CPWAIT1(); }
        else            { CPWAIT0(); }
        __syncthreads();

        const uint32_t kb = sb + KV_OFF_ + (t & 1) * KVB_;
        #pragma unroll
        for (int sub = 0; sub < 2; sub++) {
            int n0 = (2 * wid + sub) * 8;
            float acc[4] = {0.0f, 0.0f, 0.0f, 0.0f};
            #pragma unroll
            for (int ks = 0; ks < 4; ks++) {
                uint32_t bf[2];
                uint32_t so = (uint32_t)((n0 + (lane & 7)) * 128 + ks * 32 + ((lane >> 3) & 1) * 16);
                so ^= (so >> 3) & 0x70;
                ldsm2(bf, kb + so);
                mma16816(acc, qf[ks], bf);
            }
            int g = lane >> 2, tg = lane & 3;
            int col = t * NTL_ + n0 + tg * 2;
            S[g * SROW_ + col]           = acc[0] * SCALE_;
            S[g * SROW_ + col + 1]       = acc[1] * SCALE_;
            S[(g + 8) * SROW_ + col]     = acc[2] * SCALE_;
            S[(g + 8) * SROW_ + col + 1] = acc[3] * SCALE_;
        }
        __syncthreads();
    }

    // V tile 0 prefetch overlaps the softmax below
    stageKV(sb + KV_OFF_, vg, 0); CPCOMMIT();

    {
        const int jmax = nt * NTL_;
        __half* P = (__half*)(smc + P_OFF_);
        #pragma unroll
        for (int qq = 0; qq < 2; qq++) {
            int r  = 2 * wid + qq;
            int nq = q0 + r + 1;
            float m = -1e30f;
            for (int j = lane; j < nq; j += 32) m = fmaxf(m, S[r * SROW_ + j]);
            #pragma unroll
            for (int st = 16; st > 0; st >>= 1)
                m = fmaxf(m, __shfl_xor_sync(0xffffffff, m, st));
            float sum = 0.0f;
            for (int j = lane; j < jmax; j += 32) {
                float e = 0.0f;
                if (j < nq) { e = __expf(S[r * SROW_ + j] - m); sum += e; }
                int ch = j >> 3;
                uint32_t off = (uint32_t)(r * 2048 + ((ch ^ (r & 7)) * 16) + (j & 7) * 2);
                *(__half*)((char*)P + off) = __float2half_rn(e);
            }
            #pragma unroll
            for (int st = 16; st > 0; st >>= 1)
                sum += __shfl_xor_sync(0xffffffff, sum, st);
            if (lane == 0) Rinv[r] = 1.0f / sum;
        }
    }
    __syncthreads();

    float oacc[4] = {0.0f, 0.0f, 0.0f, 0.0f};
    for (int t = 0; t < nt; t++) {
        if (t + 1 < nt) { stageKV(sb + KV_OFF_ + ((t + 1) & 1) * KVB_, vg, t + 1); CPCOMMIT(); CPWAIT1(); }
        else            { CPWAIT0(); }
        __syncthreads();

        const uint32_t vb = sb + KV_OFF_ + (t & 1) * KVB_;
        #pragma unroll
        for (int ks = 0; ks < 8; ks++) {
            uint32_t pf[4];
            {
                int r  = lane & 15;
                int ch = t * 16 + 2 * ks + (lane >> 4);
                uint32_t addr = (uint32_t)(P_OFF_ + r * 2048 + ((ch ^ (r & 7)) * 16));
                ldsm4(pf, sb + addr);
            }
            uint32_t vf[2];
            {
                int kr = ks * 16 + (lane & 15);
                int cx = wid;
                uint32_t so = (uint32_t)(kr * 128 + ((cx ^ (kr & 7)) * 16));
                ldsm2t(vf, vb + so);
            }
            mma16816(oacc, pf, vf);
        }
        __syncthreads();
    }

    {
        int g = lane >> 2, tg = lane & 3;
        int col = wid * 8 + tg * 2;
        #pragma unroll
        for (int half = 0; half < 2; half++) {
            int row = g + half * 8;
            float rv = Rinv[row];
            __half2 o = __halves2half2(__float2half_rn(oacc[2 * half + 0] * rv),
                                       __float2half_rn(oacc[2 * half + 1] * rv));
            *(__half2*)(oh + ((size_t)b * S_ + q0 + row) * hrow + h * HS_ + col) = o;
        }
    }
}

// ------------------------- driver -------------------------------------------
static cudaStream_t g_s2 = nullptr;
static cudaEvent_t  g_evFork = nullptr, g_evJoin = nullptr;

static inline void wsplit_on(cudaStream_t st, const float* src, __half* dst, size_t nfloat)
{
    int n4 = (int)(nfloat / 4);
    int quarter = (n4 >> 1) >> 2;
    wsplit_k<<<(quarter + 255) / 256, 256, 0, st>>>(
        (const float4*)src, (uint4*)dst, n4);
}

extern "C" void kernel_launch(void* const* d_in, const int* in_sizes, int n_in,
                              void* d_out, int out_size)
{
    const int*   idx   = (const int*)  d_in[0];
    const float* tok   = (const float*)d_in[1];
    const float* pos   = (const float*)d_in[2];
    const float* ln1g  = (const float*)d_in[3];
    const float* ln1b  = (const float*)d_in[4];
    const float* ln2g  = (const float*)d_in[5];
    const float* ln2b  = (const float*)d_in[6];
    const float* wq    = (const float*)d_in[7];
    const float* wk    = (const float*)d_in[8];
    const float* wv    = (const float*)d_in[9];
    const float* wo    = (const float*)d_in[10];
    const float* bo    = (const float*)d_in[11];
    const float* w1    = (const float*)d_in[12];
    const float* b1    = (const float*)d_in[13];
    const float* w2    = (const float*)d_in[14];
    const float* b2    = (const float*)d_in[15];
    const float* lnfg  = (const float*)d_in[16];
    const float* lnfb  = (const float*)d_in[17];
    const float* whead = (const float*)d_in[18];
    const float* bhead = (const float*)d_in[19];
    float* out = (float*)d_out;

    float *x, *xn;
    __half *qkvh, *ah, *hh, *wh;
    cudaGetSymbolAddress((void**)&x,    g_x);
    cudaGetSymbolAddress((void**)&xn,   g_xn);
    cudaGetSymbolAddress((void**)&qkvh, g_qkvh);
    cudaGetSymbolAddress((void**)&ah,   g_ah);
    cudaGetSymbolAddress((void**)&hh,   g_hh);
    cudaGetSymbolAddress((void**)&wh,   g_wh);

    cudaFuncSetAttribute(mma_gemm_k<false,false,false,true>,  cudaFuncAttributeMaxDynamicSharedMemorySize, SMTOT_);
    cudaFuncSetAttribute(mma_gemm_k<true,true,false,false>,   cudaFuncAttributeMaxDynamicSharedMemorySize, SMTOT_);
    cudaFuncSetAttribute(mma_gemm_k<true,false,true,true>,    cudaFuncAttributeMaxDynamicSharedMemorySize, SMTOT_);
    cudaFuncSetAttribute(mma_gemm_k<true,false,false,false>,  cudaFuncAttributeMaxDynamicSharedMemorySize, SMTOT_);
    cudaFuncSetAttribute(attn_tc_k, cudaFuncAttributeMaxDynamicSharedMemorySize, ATT_SM_);

    // one-time infra (resource creation only; identical work every call)
    if (!g_s2) {
        cudaStreamCreateWithFlags(&g_s2, cudaStreamNonBlocking);
        cudaEventCreateWithFlags(&g_evFork, cudaEventDisableTiming);
        cudaEventCreateWithFlags(&g_evJoin, cudaEventDisableTiming);
    }

    dim3 blk(256);

    // ---- serial path: layer-0 weight conversion only ----
    wsplit_on(0, wq, wh + WQ_OFF_, DD_);
    wsplit_on(0, wk, wh + WK_OFF_, DD_);
    wsplit_on(0, wv, wh + WV_OFF_, DD_);
    wsplit_on(0, wo, wh + WO_OFF_, DD_);
    wsplit_on(0, w1, wh + W1_OFF_, 4 * DD_);
    wsplit_on(0, w2, wh + W2_OFF_, 4 * DD_);

    // ---- fork: layers 1-3 weights + head weight on side stream ----
    cudaEventRecord(g_evFork, 0);
    cudaStreamWaitEvent(g_s2, g_evFork, 0);
    wsplit_on(g_s2, wq + DD_,     wh + WQ_OFF_ + DD_,     3 * DD_);
    wsplit_on(g_s2, wk + DD_,     wh + WK_OFF_ + DD_,     3 * DD_);
    wsplit_on(g_s2, wv + DD_,     wh + WV_OFF_ + DD_,     3 * DD_);
    wsplit_on(g_s2, wo + DD_,     wh + WO_OFF_ + DD_,     3 * DD_);
    wsplit_on(g_s2, w1 + 4 * DD_, wh + W1_OFF_ + 4 * DD_, 12 * DD_);
    wsplit_on(g_s2, w2 + 4 * DD_, wh + W2_OFF_ + 4 * DD_, 12 * DD_);
    wsplit_on(g_s2, whead,        wh + WH_OFF_,           (size_t)D_ * V_);
    cudaEventRecord(g_evJoin, g_s2);

    embed_k<<<M_, blk>>>(idx, (const float4*)tok, (const float4*)pos, (float4*)x);

    for (int l = 0; l < L_; l++) {
        if (l == 1) cudaStreamWaitEvent(0, g_evJoin, 0);  // join before layer 1

        size_t oq = WQ_OFF_ + (size_t)l * DD_;
        size_t oo = WO_OFF_ + (size_t)l * DD_;
        size_t o1 = W1_OFF_ + (size_t)l * 4 * DD_;
        size_t o2 = W2_OFF_ + (size_t)l * 4 * DD_;

        layernorm_k<<<M_, blk>>>((const float4*)x, (const float4*)(ln1g + l * D_),
                                 (const float4*)(ln1b + l * D_), (float4*)xn,
                                 (uint2*)ah);

        // fused QKV -> fp16 qkv slabs
        mma_gemm_k<false,false,false,true><<<dim3(M_/128, D_/256, 3), blk, SMTOT_>>>(
            M_, D_, D_, ah, wh + oq, nullptr, nullptr, nullptr,
            (__half2*)qkvh, 4 * DD_, 0, MD_ / 2);

        attn_tc_k<<<dim3(S_ / QT_, H_, B_), 256, ATT_SM_>>>(qkvh, ah);

        // x = xn + att @ wo + bo
        mma_gemm_k<true,true,false,false><<<dim3(M_/128, D_/256), blk, SMTOT_>>>(
            M_, D_, D_, ah, wh + oo, bo + l * D_, xn, x,
            nullptr, 0, 0, 0);

        layernorm_k<<<M_, blk>>>((const float4*)x, (const float4*)(ln2g + l * D_),
                                 (const float4*)(ln2b + l * D_), (float4*)xn,
                                 (uint2*)ah);

        // h = relu(xn @ w1 + b1)  -> fp16 directly
        mma_gemm_k<true,false,true,true><<<dim3(M_/128, DFF_/256), blk, SMTOT_>>>(
            M_, DFF_, D_, ah, wh + o1,
            b1 + (size_t)l * DFF_, nullptr, nullptr,
            (__half2*)hh, 0, 0, 0);

        // x = xn + h @ w2 + b2
        mma_gemm_k<true,true,false,false><<<dim3(M_/128, D_/256), blk, SMTOT_>>>(
            M_, D_, DFF_, hh, wh + o2,
            b2 + l * D_, xn, x, nullptr, 0, 0, 0);
    }

    layernorm_k<<<M_, blk>>>((const float4*)x, (const float4*)lnfg,
                             (const float4*)lnfb, (float4*)xn,
                             (uint2*)ah);

    // logits = xn @ w_head + b_head
    mma_gemm_k<true,false,false,false><<<dim3(M_/128, V_/256), blk, SMTOT_>>>(
        M_, V_, D_, ah, wh + WH_OFF_,
        bhead, nullptr, out, nullptr, 0, 0, 0);
}

// round 14
// speedup vs baseline: 2.5442x; 1.0036x over previous
#include <cuda_runtime.h>
#include <cuda_fp16.h>
#include <cstdint>
#include <math.h>

// ---------------------------------------------------------------------------
// MinGPT forward.  B=4, S=1024, D=1024, H=16, HS=64, L=4, DFF=4096, V=32000.
// Round 14: fused embed+LN (no x round-trip for layer 0), warp-shuffle LN
// reductions, all weight conversion forked (2 join points).
// ---------------------------------------------------------------------------

#define B_  4
#define S_  1024
#define D_  1024
#define H_  16
#define HS_ 64
#define L_  4
#define DFF_ 4096
#define V_  32000
#define M_  (B_ * S_)
#define MD_ ((size_t)M_ * D_)
#define EPS_ 1e-5f
#define SCALE_ 0.03125f        // D^-0.5 = 1/32 (reference uses d_model)

// ------------------------- scratch -----------------------------------------
__device__ float g_x  [M_ * D_];
__device__ float g_xn [M_ * D_];

__device__ __align__(16) __half g_qkvh[3 * M_ * D_];
__device__ __align__(16) __half g_ah[M_ * D_];
__device__ __align__(16) __half g_hh[M_ * DFF_];

#define DD_      ((size_t)D_ * D_)
#define WQ_OFF_  ((size_t)0)
#define WK_OFF_  (4 * DD_)
#define WV_OFF_  (8 * DD_)
#define WO_OFF_  (12 * DD_)
#define W1_OFF_  (16 * DD_)
#define W2_OFF_  (32 * DD_)
#define WH_OFF_  (48 * DD_)
#define WT_TOT_  (48 * DD_ + (size_t)D_ * V_)
__device__ __align__(16) __half g_wh[WT_TOT_];

// ------------------------- PTX helpers --------------------------------------
__device__ __forceinline__ uint32_t smem_u32(const void* p) {
    uint32_t a;
    asm("{ .reg .u64 t; cvta.to.shared.u64 t, %1; cvt.u32.u64 %0, t; }"
        : "=r"(a) : "l"(p));
    return a;
}
#define CP16(dst, src) \
    asm volatile("cp.async.cg.shared.global [%0], [%1], 16;" :: "r"(dst), "l"(src))
#define CPCOMMIT() asm volatile("cp.async.commit_group;" ::: "memory")
#define CPWAIT0()  asm volatile("cp.async.wait_group 0;" ::: "memory")
#define CPWAIT1()  asm volatile("cp.async.wait_group 1;" ::: "memory")
#define CPWAIT2()  asm volatile("cp.async.wait_group 2;" ::: "memory")

__device__ __forceinline__ void ldsm4(uint32_t* r, uint32_t addr) {
    asm volatile("ldmatrix.sync.aligned.m8n8.x4.shared.b16 {%0,%1,%2,%3}, [%4];"
        : "=r"(r[0]), "=r"(r[1]), "=r"(r[2]), "=r"(r[3]) : "r"(addr));
}
__device__ __forceinline__ void ldsm4t(uint32_t* r, uint32_t addr) {
    asm volatile("ldmatrix.sync.aligned.m8n8.x4.trans.shared.b16 {%0,%1,%2,%3}, [%4];"
        : "=r"(r[0]), "=r"(r[1]), "=r"(r[2]), "=r"(r[3]) : "r"(addr));
}
__device__ __forceinline__ void ldsm2(uint32_t* r, uint32_t addr) {
    asm volatile("ldmatrix.sync.aligned.m8n8.x2.shared.b16 {%0,%1}, [%2];"
        : "=r"(r[0]), "=r"(r[1]) : "r"(addr));
}
__device__ __forceinline__ void ldsm2t(uint32_t* r, uint32_t addr) {
    asm volatile("ldmatrix.sync.aligned.m8n8.x2.trans.shared.b16 {%0,%1}, [%2];"
        : "=r"(r[0]), "=r"(r[1]) : "r"(addr));
}
__device__ __forceinline__ void mma16816(float* d, const uint32_t* a, const uint32_t* b) {
    asm volatile(
        "mma.sync.aligned.m16n8k16.row.col.f32.f16.f16.f32 "
        "{%0,%1,%2,%3}, {%4,%5,%6,%7}, {%8,%9}, {%0,%1,%2,%3};"
        : "+f"(d[0]), "+f"(d[1]), "+f"(d[2]), "+f"(d[3])
        : "r"(a[0]), "r"(a[1]), "r"(a[2]), "r"(a[3]), "r"(b[0]), "r"(b[1]));
}

__device__ __forceinline__ uint32_t pack2h(float a, float b) {
    __half2 h = __halves2half2(__float2half_rn(a), __float2half_rn(b));
    return *(uint32_t*)&h;
}

// block reduction over 256 threads via warp shuffles; ws = 8-float scratch
__device__ __forceinline__ float blk_sum(float v, float* ws, int tid) {
    #pragma unroll
    for (int st = 16; st > 0; st >>= 1)
        v += __shfl_xor_sync(0xffffffff, v, st);
    if ((tid & 31) == 0) ws[tid >> 5] = v;
    __syncthreads();
    if (tid < 32) {
        float w = (tid < 8) ? ws[tid] : 0.0f;
        #pragma unroll
        for (int st = 4; st > 0; st >>= 1)
            w += __shfl_xor_sync(0xffffffff, w, st);
        if (tid == 0) ws[0] = w;
    }
    __syncthreads();
    return ws[0];
}

// ------------------------- LN core (shared by both variants) -----------------
__device__ __forceinline__ void ln_finish(
    float4 xv, int tid, size_t i,
    const float4* __restrict__ g, const float4* __restrict__ bb,
    float4* __restrict__ y, uint2* __restrict__ oh,
    float* ws1, float* ws2)
{
    float s = xv.x + xv.y + xv.z + xv.w;
    float mu = blk_sum(s, ws1, tid) * (1.0f / D_);

    float dx = xv.x - mu, dy = xv.y - mu, dz = xv.z - mu, dw = xv.w - mu;
    float s2 = dx * dx + dy * dy + dz * dz + dw * dw;
    float var = blk_sum(s2, ws2, tid) * (1.0f / D_);
    float inv = rsqrtf(var + EPS_);

    float4 gv = g[tid], bv = bb[tid];
    float4 o;
    o.x = dx * inv * gv.x + bv.x;
    o.y = dy * inv * gv.y + bv.y;
    o.z = dz * inv * gv.z + bv.z;
    o.w = dw * inv * gv.w + bv.w;
    y[i] = o;

    uint2 hp;
    hp.x = pack2h(o.x, o.y);
    hp.y = pack2h(o.z, o.w);
    oh[i] = hp;
}

// ------------------------- layer norm ----------------------------------------
__global__ __launch_bounds__(256) void layernorm_k(
    const float4* __restrict__ x, const float4* __restrict__ g,
    const float4* __restrict__ bb, float4* __restrict__ y,
    uint2* __restrict__ oh)
{
    __shared__ float ws1[8], ws2[8];
    int row = blockIdx.x, tid = threadIdx.x;
    size_t i = (size_t)row * 256 + tid;
    float4 xv = x[i];
    ln_finish(xv, tid, i, g, bb, y, oh, ws1, ws2);
}

// ------------------------- fused embedding + layer norm ----------------------
__global__ __launch_bounds__(256) void embed_ln_k(
    const int* __restrict__ idx, const float4* __restrict__ tok,
    const float4* __restrict__ pos,
    const float4* __restrict__ g, const float4* __restrict__ bb,
    float4* __restrict__ y, uint2* __restrict__ oh)
{
    __shared__ float ws1[8], ws2[8];
    int row = blockIdx.x, tid = threadIdx.x;
    int s   = row & (S_ - 1);
    int t   = idx[row];
    float4 tv = tok[(size_t)t * 256 + tid];
    float4 pv = pos[(size_t)s * 256 + tid];
    float4 xv;
    xv.x = tv.x + pv.x; xv.y = tv.y + pv.y;
    xv.z = tv.z + pv.z; xv.w = tv.w + pv.w;
    size_t i = (size_t)row * 256 + tid;
    ln_finish(xv, tid, i, g, bb, y, oh, ws1, ws2);
}

// ------------------------- fp32 -> fp16 (weights), 16B stores, MLP=4 --------
__global__ __launch_bounds__(256) void wsplit_k(
    const float4* __restrict__ x, uint4* __restrict__ h, int n4)
{
    int npair = n4 >> 1;
    int quarter = npair >> 2;
    int i = blockIdx.x * 256 + threadIdx.x;
    if (i >= quarter) return;
    #pragma unroll
    for (int m = 0; m < 4; m++) {
        int p = i + m * quarter;
        float4 v0 = x[2 * p];
        float4 v1 = x[2 * p + 1];
        uint4 o;
        o.x = pack2h(v0.x, v0.y);
        o.y = pack2h(v0.z, v0.w);
        o.z = pack2h(v1.x, v1.y);
        o.w = pack2h(v1.z, v1.w);
        h[p] = o;
    }
}

// ------------------------- mma.sync GEMM (3-stage pipeline) ------------------
#define ATILEB_ 16384
#define BTILEB_ 32768
#define BUFB_   (ATILEB_ + BTILEB_)        // 48 KB
#define SMTOT_  (3 * BUFB_)                // 144 KB

template<bool BIAS, bool RES, bool RELU, bool OHALF>
__global__ __launch_bounds__(256, 1) void mma_gemm_k(
    int M, int N, int K,
    const __half* __restrict__ Ah,
    const __half* __restrict__ Bw,
    const float* __restrict__ bias, const float* __restrict__ res,
    float* __restrict__ C,
    __half2* __restrict__ Oh,
    size_t bzS, size_t czS, size_t ozS)
{
    extern __shared__ char smem[];
    const uint32_t sb = smem_u32(smem);
    const int tid = threadIdx.x, wid = tid >> 5, lane = tid & 31;
    const int mb = blockIdx.x, nb = blockIdx.y;
    Bw += blockIdx.z * bzS;
    C  += blockIdx.z * czS;
    if (OHALF) Oh += blockIdx.z * ozS;
    const size_t ar0 = (size_t)mb * 128, bc0 = (size_t)nb * 256;
    const int wm = (wid >> 2) * 64, wn = (wid & 3) * 64;

    float acc[4][8][4];
    #pragma unroll
    for (int i = 0; i < 4; i++)
        #pragma unroll
        for (int j = 0; j < 8; j++)
            #pragma unroll
            for (int e = 0; e < 4; e++) acc[i][j][e] = 0.0f;

    const int nch = K >> 6;

    auto fill = [&](int buf, int c) {
        const size_t kof = (size_t)c << 6;
        const uint32_t bb = sb + buf * BUFB_;
        #pragma unroll
        for (int i = 0; i < 4; i++) {
            int id = tid + 256 * i;
            int r  = id >> 3;
            int cx = id & 7;
            uint32_t so = (uint32_t)(r * 128 + cx * 16);
            so ^= (so >> 3) & 0x70;
            size_t ai = (ar0 + r) * (size_t)K + kof + cx * 8;
            CP16(bb + so, Ah + ai);
        }
        #pragma unroll
        for (int i = 0; i < 8; i++) {
            int id = tid + 256 * i;
            int kr = id >> 5;
            int cx = id & 31;
            uint32_t so = (uint32_t)(kr * 512 + ((cx ^ (kr & 31)) * 16));
            size_t bi = (kof + kr) * (size_t)N + bc0 + cx * 8;
            CP16(bb + ATILEB_ + so, Bw + bi);
        }
    };

    fill(0, 0); CPCOMMIT();
    fill(1, 1); CPCOMMIT();

    uint32_t fa[4][4], fb[8][2];
    const int arow = wm + (lane & 15);
    const int akb  = (lane >> 4) * 16;
    const int krl  = lane & 15;
    const int nsel = lane >> 4;

    int buf = 0;
    for (int c = 0; c < nch; c++) {
        if (c + 2 < nch) {
            int nbuf = buf + 2; if (nbuf >= 3) nbuf -= 3;
            fill(nbuf, c + 2); CPCOMMIT(); CPWAIT2();
        } else if (c + 1 < nch) { CPWAIT1(); }
        else                    { CPWAIT0(); }
        __syncthreads();

        const uint32_t base = sb + buf * BUFB_;
        #pragma unroll
        for (int ks = 0; ks < 4; ks++) {
            #pragma unroll
            for (int i = 0; i < 4; i++) {
                uint32_t so = (uint32_t)((arow + i * 16) * 128 + ks * 32 + akb);
                so ^= (so >> 3) & 0x70;
                ldsm4(fa[i], base + so);
            }
            const uint32_t krow = (uint32_t)(ks * 16 + krl);
            #pragma unroll
            for (int j2 = 0; j2 < 4; j2++) {
                uint32_t cx = (uint32_t)((wn >> 3) + 2 * j2 + nsel);
                uint32_t so = krow * 512 + ((cx ^ (krow & 31)) * 16);
                uint32_t r[4];
                ldsm4t(r, base + ATILEB_ + so);
                fb[2 * j2 + 0][0] = r[0]; fb[2 * j2 + 0][1] = r[1];
                fb[2 * j2 + 1][0] = r[2]; fb[2 * j2 + 1][1] = r[3];
            }
            #pragma unroll
            for (int i = 0; i < 4; i++)
                #pragma unroll
                for (int j = 0; j < 8; j++)
                    mma16816(acc[i][j], fa[i], fb[j]);
        }
        __syncthreads();
        if (++buf == 3) buf = 0;
    }

    const int g  = lane >> 2, tg = lane & 3;
    const size_t row0 = ar0 + wm, col0 = bc0 + wn;
    #pragma unroll
    for (int i = 0; i < 4; i++) {
        #pragma unroll
        for (int j = 0; j < 8; j++) {
            size_t col = col0 + j * 8 + tg * 2;
            float bx = 0.0f, by = 0.0f;
            if (BIAS) { bx = bias[col]; by = bias[col + 1]; }
            #pragma unroll
            for (int half = 0; half < 2; half++) {
                size_t row = row0 + i * 16 + g + half * 8;
                float vx = acc[i][j][2 * half + 0] + bx;
                float vy = acc[i][j][2 * half + 1] + by;
                size_t gi = row * (size_t)N + col;
                if (RES) { vx += res[gi]; vy += res[gi + 1]; }
                if (RELU) { vx = fmaxf(vx, 0.0f); vy = fmaxf(vy, 0.0f); }
                if (OHALF) {
                    Oh[gi >> 1] = __halves2half2(__float2half_rn(vx),
                                                 __float2half_rn(vy));
                } else {
                    float2 o; o.x = vx; o.y = vy;
                    *(float2*)(C + gi) = o;
                }
            }
        }
    }
}

// ------------------------- tensor-core attention -----------------------------
#define QT_    16
#define NTL_   128
#define SROW_  1032
#define SBY_   (QT_ * SROW_ * 4)
#define P_OFF_ SBY_
#define Q_OFF_ (P_OFF_ + QT_ * 2048)
#define KV_OFF_ (Q_OFF_ + 2048)
#define KVB_   16384
#define RINV_OFF_ (KV_OFF_ + 2 * KVB_)
#define ATT_SM_ (RINV_OFF_ + 64)

__global__ __launch_bounds__(256, 1) void attn_tc_k(
    const __half* __restrict__ qkvh, __half* __restrict__ oh)
{
    extern __shared__ char smc[];
    const uint32_t sb = smem_u32(smc);
    float* S    = (float*)smc;
    float* Rinv = (float*)(smc + RINV_OFF_);

    const int tid = threadIdx.x, wid = tid >> 5, lane = tid & 31;
    const int qt = (int)gridDim.x - 1 - (int)blockIdx.x;
    const int h = blockIdx.y, b = blockIdx.z;
    const int q0 = qt * QT_;
    const int nt = (q0 + QT_ + NTL_ - 1) / NTL_;

    const size_t hrow = (size_t)H_ * HS_;
    const __half* qg = qkvh + ((size_t)b * S_ + q0) * hrow + h * HS_;
    const __half* kg = qkvh + MD_     + (size_t)b * S_ * hrow + h * HS_;
    const __half* vg = qkvh + 2 * MD_ + (size_t)b * S_ * hrow + h * HS_;

    auto stageKV = [&](uint32_t dst, const __half* src, int t) {
        int j0 = t * NTL_;
        #pragma unroll
        for (int i = 0; i < 4; i++) {
            int id = tid + 256 * i;
            int r  = id >> 3;
            int cx = id & 7;
            uint32_t so = (uint32_t)(r * 128 + cx * 16);
            so ^= (so >> 3) & 0x70;
            CP16(dst + so, src + (size_t)(j0 + r) * hrow + cx * 8);
        }
    };

    if (tid < 128) {
        int r = tid >> 3, cx = tid & 7;
        uint32_t so = (uint32_t)(r * 128 + cx * 16);
        so ^= (so >> 3) & 0x70;
        CP16(sb + Q_OFF_ + so, qg + (size_t)r * hrow + cx * 8);
    }
    CPCOMMIT();
    stageKV(sb + KV_OFF_, kg, 0); CPCOMMIT();
    CPWAIT1();
    __syncthreads();

    uint32_t qf[4][4];
    {
        const int arow = lane & 15;
        const int akb  = (lane >> 4) * 16;
        #pragma unroll
        for (int ks = 0; ks < 4; ks++) {
            uint32_t so = (uint32_t)(arow * 128 + ks * 32 + akb);
            so ^= (so >> 3) & 0x70;
            ldsm4(qf[ks], sb + Q_OFF_ + so);
        }
    }

    for (int t = 0; t < nt; t++) {
        if (t + 1 < nt) { stageKV(sb + KV_OFF_ + ((t + 1) & 1) * KVB_, kg, t + 1); CPCOMMIT(); CPWAIT1(); }
        else            { CPWAIT0(); }
        __syncthreads();

        const uint32_t kb = sb + KV_OFF_ + (t & 1) * KVB_;
        #pragma unroll
        for (int sub = 0; sub < 2; sub++) {
            int n0 = (2 * wid + sub) * 8;
            float acc[4] = {0.0f, 0.0f, 0.0f, 0.0f};
            #pragma unroll
            for (int ks = 0; ks < 4; ks++) {
                uint32_t bf[2];
                uint32_t so = (uint32_t)((n0 + (lane & 7)) * 128 + ks * 32 + ((lane >> 3) & 1) * 16);
                so ^= (so >> 3) & 0x70;
                ldsm2(bf, kb + so);
                mma16816(acc, qf[ks], bf);
            }
            int g = lane >> 2, tg = lane & 3;
            int col = t * NTL_ + n0 + tg * 2;
            S[g * SROW_ + col]           = acc[0] * SCALE_;
            S[g * SROW_ + col + 1]       = acc[1] * SCALE_;
            S[(g + 8) * SROW_ + col]     = acc[2] * SCALE_;
            S[(g + 8) * SROW_ + col + 1] = acc[3] * SCALE_;
        }
        __syncthreads();
    }

    // V tile 0 prefetch overlaps the softmax below
    stageKV(sb + KV_OFF_, vg, 0); CPCOMMIT();

    {
        const int jmax = nt * NTL_;
        __half* P = (__half*)(smc + P_OFF_);
        #pragma unroll
        for (int qq = 0; qq < 2; qq++) {
            int r  = 2 * wid + qq;
            int nq = q0 + r + 1;
            float m = -1e30f;
            for (int j = lane; j < nq; j += 32) m = fmaxf(m, S[r * SROW_ + j]);
            #pragma unroll
            for (int st = 16; st > 0; st >>= 1)
                m = fmaxf(m, __shfl_xor_sync(0xffffffff, m, st));
            float sum = 0.0f;
            for (int j = lane; j < jmax; j += 32) {
                float e = 0.0f;
                if (j < nq) { e = __expf(S[r * SROW_ + j] - m); sum += e; }
                int ch = j >> 3;
                uint32_t off = (uint32_t)(r * 2048 + ((ch ^ (r & 7)) * 16) + (j & 7) * 2);
                *(__half*)((char*)P + off) = __float2half_rn(e);
            }
            #pragma unroll
            for (int st = 16; st > 0; st >>= 1)
                sum += __shfl_xor_sync(0xffffffff, sum, st);
            if (lane == 0) Rinv[r] = 1.0f / sum;
        }
    }
    __syncthreads();

    float oacc[4] = {0.0f, 0.0f, 0.0f, 0.0f};
    for (int t = 0; t < nt; t++) {
        if (t + 1 < nt) { stageKV(sb + KV_OFF_ + ((t + 1) & 1) * KVB_, vg, t + 1); CPCOMMIT(); CPWAIT1(); }
        else            { CPWAIT0(); }
        __syncthreads();

        const uint32_t vb = sb + KV_OFF_ + (t & 1) * KVB_;
        #pragma unroll
        for (int ks = 0; ks < 8; ks++) {
            uint32_t pf[4];
            {
                int r  = lane & 15;
                int ch = t * 16 + 2 * ks + (lane >> 4);
                uint32_t addr = (uint32_t)(P_OFF_ + r * 2048 + ((ch ^ (r & 7)) * 16));
                ldsm4(pf, sb + addr);
            }
            uint32_t vf[2];
            {
                int kr = ks * 16 + (lane & 15);
                int cx = wid;
                uint32_t so = (uint32_t)(kr * 128 + ((cx ^ (kr & 7)) * 16));
                ldsm2t(vf, vb + so);
            }
            mma16816(oacc, pf, vf);
        }
        __syncthreads();
    }

    {
        int g = lane >> 2, tg = lane & 3;
        int col = wid * 8 + tg * 2;
        #pragma unroll
        for (int half = 0; half < 2; half++) {
            int row = g + half * 8;
            float rv = Rinv[row];
            __half2 o = __halves2half2(__float2half_rn(oacc[2 * half + 0] * rv),
                                       __float2half_rn(oacc[2 * half + 1] * rv));
            *(__half2*)(oh + ((size_t)b * S_ + q0 + row) * hrow + h * HS_ + col) = o;
        }
    }
}

// ------------------------- driver -------------------------------------------
static cudaStream_t g_s2 = nullptr;
static cudaEvent_t  g_evFork = nullptr, g_evJ0 = nullptr, g_evJ1 = nullptr;

static inline void wsplit_on(cudaStream_t st, const float* src, __half* dst, size_t nfloat)
{
    int n4 = (int)(nfloat / 4);
    int quarter = (n4 >> 1) >> 2;
    wsplit_k<<<(quarter + 255) / 256, 256, 0, st>>>(
        (const float4*)src, (uint4*)dst, n4);
}

extern "C" void kernel_launch(void* const* d_in, const int* in_sizes, int n_in,
                              void* d_out, int out_size)
{
    const int*   idx   = (const int*)  d_in[0];
    const float* tok   = (const float*)d_in[1];
    const float* pos   = (const float*)d_in[2];
    const float* ln1g  = (const float*)d_in[3];
    const float* ln1b  = (const float*)d_in[4];
    const float* ln2g  = (const float*)d_in[5];
    const float* ln2b  = (const float*)d_in[6];
    const float* wq    = (const float*)d_in[7];
    const float* wk    = (const float*)d_in[8];
    const float* wv    = (const float*)d_in[9];
    const float* wo    = (const float*)d_in[10];
    const float* bo    = (const float*)d_in[11];
    const float* w1    = (const float*)d_in[12];
    const float* b1    = (const float*)d_in[13];
    const float* w2    = (const float*)d_in[14];
    const float* b2    = (const float*)d_in[15];
    const float* lnfg  = (const float*)d_in[16];
    const float* lnfb  = (const float*)d_in[17];
    const float* whead = (const float*)d_in[18];
    const float* bhead = (const float*)d_in[19];
    float* out = (float*)d_out;

    float *x, *xn;
    __half *qkvh, *ah, *hh, *wh;
    cudaGetSymbolAddress((void**)&x,    g_x);
    cudaGetSymbolAddress((void**)&xn,   g_xn);
    cudaGetSymbolAddress((void**)&qkvh, g_qkvh);
    cudaGetSymbolAddress((void**)&ah,   g_ah);
    cudaGetSymbolAddress((void**)&hh,   g_hh);
    cudaGetSymbolAddress((void**)&wh,   g_wh);

    cudaFuncSetAttribute(mma_gemm_k<false,false,false,true>,  cudaFuncAttributeMaxDynamicSharedMemorySize, SMTOT_);
    cudaFuncSetAttribute(mma_gemm_k<true,true,false,false>,   cudaFuncAttributeMaxDynamicSharedMemorySize, SMTOT_);
    cudaFuncSetAttribute(mma_gemm_k<true,false,true,true>,    cudaFuncAttributeMaxDynamicSharedMemorySize, SMTOT_);
    cudaFuncSetAttribute(mma_gemm_k<true,false,false,false>,  cudaFuncAttributeMaxDynamicSharedMemorySize, SMTOT_);
    cudaFuncSetAttribute(attn_tc_k, cudaFuncAttributeMaxDynamicSharedMemorySize, ATT_SM_);

    if (!g_s2) {
        cudaStreamCreateWithFlags(&g_s2, cudaStreamNonBlocking);
        cudaEventCreateWithFlags(&g_evFork, cudaEventDisableTiming);
        cudaEventCreateWithFlags(&g_evJ0,   cudaEventDisableTiming);
        cudaEventCreateWithFlags(&g_evJ1,   cudaEventDisableTiming);
    }

    dim3 blk(256);

    // ---- fork ALL weight conversion onto the side stream ----
    cudaEventRecord(g_evFork, 0);
    cudaStreamWaitEvent(g_s2, g_evFork, 0);
    // layer-0 weights first (needed soonest)
    wsplit_on(g_s2, wq, wh + WQ_OFF_, DD_);
    wsplit_on(g_s2, wk, wh + WK_OFF_, DD_);
    wsplit_on(g_s2, wv, wh + WV_OFF_, DD_);
    wsplit_on(g_s2, wo, wh + WO_OFF_, DD_);
    wsplit_on(g_s2, w1, wh + W1_OFF_, 4 * DD_);
    wsplit_on(g_s2, w2, wh + W2_OFF_, 4 * DD_);
    cudaEventRecord(g_evJ0, g_s2);
    // layers 1-3 + head weight
    wsplit_on(g_s2, wq + DD_,     wh + WQ_OFF_ + DD_,     3 * DD_);
    wsplit_on(g_s2, wk + DD_,     wh + WK_OFF_ + DD_,     3 * DD_);
    wsplit_on(g_s2, wv + DD_,     wh + WV_OFF_ + DD_,     3 * DD_);
    wsplit_on(g_s2, wo + DD_,     wh + WO_OFF_ + DD_,     3 * DD_);
    wsplit_on(g_s2, w1 + 4 * DD_, wh + W1_OFF_ + 4 * DD_, 12 * DD_);
    wsplit_on(g_s2, w2 + 4 * DD_, wh + W2_OFF_ + 4 * DD_, 12 * DD_);
    wsplit_on(g_s2, whead,        wh + WH_OFF_,           (size_t)D_ * V_);
    cudaEventRecord(g_evJ1, g_s2);

    // ---- layer 0 front: fused embed + LN1 (overlaps the conversions) ----
    embed_ln_k<<<M_, blk>>>(idx, (const float4*)tok, (const float4*)pos,
                            (const float4*)ln1g, (const float4*)ln1b,
                            (float4*)xn, (uint2*)ah);

    for (int l = 0; l < L_; l++) {
        if (l == 0) cudaStreamWaitEvent(0, g_evJ0, 0);  // layer-0 weights ready
        if (l == 1) cudaStreamWaitEvent(0, g_evJ1, 0);  // all weights ready

        size_t oq = WQ_OFF_ + (size_t)l * DD_;
        size_t oo = WO_OFF_ + (size_t)l * DD_;
        size_t o1 = W1_OFF_ + (size_t)l * 4 * DD_;
        size_t o2 = W2_OFF_ + (size_t)l * 4 * DD_;

        if (l > 0)
            layernorm_k<<<M_, blk>>>((const float4*)x, (const float4*)(ln1g + l * D_),
                                     (const float4*)(ln1b + l * D_), (float4*)xn,
                                     (uint2*)ah);

        // fused QKV -> fp16 qkv slabs
        mma_gemm_k<false,false,false,true><<<dim3(M_/128, D_/256, 3), blk, SMTOT_>>>(
            M_, D_, D_, ah, wh + oq, nullptr, nullptr, nullptr,
            (__half2*)qkvh, 4 * DD_, 0, MD_ / 2);

        attn_tc_k<<<dim3(S_ / QT_, H_, B_), 256, ATT_SM_>>>(qkvh, ah);

        // x = xn + att @ wo + bo
        mma_gemm_k<true,true,false,false><<<dim3(M_/128, D_/256), blk, SMTOT_>>>(
            M_, D_, D_, ah, wh + oo, bo + l * D_, xn, x,
            nullptr, 0, 0, 0);

        layernorm_k<<<M_, blk>>>((const float4*)x, (const float4*)(ln2g + l * D_),
                                 (const float4*)(ln2b + l * D_), (float4*)xn,
                                 (uint2*)ah);

        // h = relu(xn @ w1 + b1)  -> fp16 directly
        mma_gemm_k<true,false,true,true><<<dim3(M_/128, DFF_/256), blk, SMTOT_>>>(
            M_, DFF_, D_, ah, wh + o1,
            b1 + (size_t)l * DFF_, nullptr, nullptr,
            (__half2*)hh, 0, 0, 0);

        // x = xn + h @ w2 + b2
        mma_gemm_k<true,true,false,false><<<dim3(M_/128, D_/256), blk, SMTOT_>>>(
            M_, D_, DFF_, hh, wh + o2,
            b2 + l * D_, xn, x, nullptr, 0, 0, 0);
    }

    layernorm_k<<<M_, blk>>>((const float4*)x, (const float4*)lnfg,
                             (const float4*)lnfb, (float4*)xn,
                             (uint2*)ah);

    // logits = xn @ w_head + b_head
    mma_gemm_k<true,false,false,false><<<dim3(M_/128, V_/256), blk, SMTOT_>>>(
        M_, V_, D_, ah, wh + WH_OFF_,
        bhead, nullptr, out, nullptr, 0, 0, 0);
}